// round 14
// baseline (speedup 1.0000x reference)
#include <cuda_runtime.h>
#include <cuda_fp16.h>
#include <math.h>
#include <stdint.h>

#define D_MODEL 1024
#define N_HEADS 16
#define D_K 64
#define D_FF 4096
#define N_LAYERS 6
#define BATCH 4
#define SEQ 1024
#define ROWS (BATCH * SEQ)   // 4096

// ---------------- scratch (device globals; no allocation allowed) ----------
__device__ float g_x[ROWS * D_MODEL];                 // residual stream (fp32)
__device__ float g_t[ROWS * D_MODEL];                 // pre-LN gemm output
__device__ __half g_qkvh[(size_t)ROWS * 3 * D_MODEL]; // QKV fp16 hi
__device__ __half g_qkvl[(size_t)ROWS * 3 * D_MODEL]; // QKV fp16 lo
__device__ __half g_ah[(size_t)ROWS * D_MODEL];       // activation hi
__device__ __half g_al[(size_t)ROWS * D_MODEL];       // activation lo
__device__ __half g_hh[(size_t)ROWS * D_FF];          // ffn hidden hi

// transposed weights: [N,K] K-major fp16
__device__ __half g_wqkvt[6u*3072*1024];
__device__ __half g_wot[6u*1024*1024];
__device__ __half g_w1t[6u*4096*1024];
__device__ __half g_w2t[6u*4096*1024];
__device__ float g_bqkv[6 * 3072];

// ---------------- PTX helpers ------------------------------------------------
__device__ __forceinline__ uint32_t smem_u32(const void* p) {
    uint32_t a;
    asm("{ .reg .u64 t; cvta.to.shared.u64 t, %1; cvt.u32.u64 %0, t; }"
        : "=r"(a) : "l"(p));
    return a;
}

__device__ __forceinline__ void cp16(uint32_t s, const void* g) {
    asm volatile("cp.async.cg.shared.global [%0], [%1], 16;"
                 :: "r"(s), "l"(g) : "memory");
}

__device__ __forceinline__ void ldsm4(uint32_t* r, uint32_t addr) {
    asm volatile("ldmatrix.sync.aligned.m8n8.x4.shared.b16 {%0,%1,%2,%3}, [%4];"
                 : "=r"(r[0]), "=r"(r[1]), "=r"(r[2]), "=r"(r[3]) : "r"(addr));
}

__device__ __forceinline__ void mma16816(float* c, const uint32_t* a,
                                         const uint32_t* b) {
    asm volatile(
        "mma.sync.aligned.m16n8k16.row.col.f32.f16.f16.f32 "
        "{%0,%1,%2,%3}, {%4,%5,%6,%7}, {%8,%9}, {%0,%1,%2,%3};"
        : "+f"(c[0]), "+f"(c[1]), "+f"(c[2]), "+f"(c[3])
        : "r"(a[0]), "r"(a[1]), "r"(a[2]), "r"(a[3]), "r"(b[0]), "r"(b[1]));
}

// f16-accumulate variant: D/C are 2 x b32 (4 halves)
__device__ __forceinline__ void mma16816_h(uint32_t* c, const uint32_t* a,
                                           const uint32_t* b) {
    asm volatile(
        "mma.sync.aligned.m16n8k16.row.col.f16.f16.f16.f16 "
        "{%0,%1}, {%2,%3,%4,%5}, {%6,%7}, {%0,%1};"
        : "+r"(c[0]), "+r"(c[1])
        : "r"(a[0]), "r"(a[1]), "r"(a[2]), "r"(a[3]), "r"(b[0]), "r"(b[1]));
}

// split a float4 into fp16 hi/lo pairs, store 8B each
__device__ __forceinline__ void store_split4(__half* H, __half* L,
                                             size_t idx, float4 v) {
    __half2 h0 = __floats2half2_rn(v.x, v.y);
    __half2 h1 = __floats2half2_rn(v.z, v.w);
    float2 f0 = __half22float2(h0);
    float2 f1 = __half22float2(h1);
    __half2 l0 = __floats2half2_rn(v.x - f0.x, v.y - f0.y);
    __half2 l1 = __floats2half2_rn(v.z - f1.x, v.w - f1.y);
    uint2 hh, ll;
    hh.x = *reinterpret_cast<uint32_t*>(&h0);
    hh.y = *reinterpret_cast<uint32_t*>(&h1);
    ll.x = *reinterpret_cast<uint32_t*>(&l0);
    ll.y = *reinterpret_cast<uint32_t*>(&l1);
    *(uint2*)(H + idx) = hh;
    *(uint2*)(L + idx) = ll;
}

// split 2 floats into fp16 hi/lo half2 (as uint32)
__device__ __forceinline__ void split2_h(float a, float b,
                                         uint32_t& hi, uint32_t& lo) {
    __half2 h = __floats2half2_rn(a, b);
    float2 f = __half22float2(h);
    __half2 l = __floats2half2_rn(a - f.x, b - f.y);
    hi = *reinterpret_cast<uint32_t*>(&h);
    lo = *reinterpret_cast<uint32_t*>(&l);
}

// ---------------- single-launch weight prep (transpose + fp16 convert) ------
__global__ void prep_weights_kernel(
    const float* __restrict__ wq, const float* __restrict__ wk,
    const float* __restrict__ wv, const float* __restrict__ wo,
    const float* __restrict__ w1, const float* __restrict__ w2,
    __half* __restrict__ qkvt, __half* __restrict__ wot,
    __half* __restrict__ w1t,  __half* __restrict__ w2t) {
    __shared__ float t[32][33];
    const int tile = blockIdx.x;       // 0..12287
    const int layer = blockIdx.z;

    const float* W; __half* T;
    int K, N, row_off, tt; size_t lstride;
    if (tile < 1024)      { W = wq; T = qkvt; K = 1024; N = 1024;
                            row_off = 0;    lstride = (size_t)3072*1024; tt = tile; }
    else if (tile < 2048) { W = wk; T = qkvt; K = 1024; N = 1024;
                            row_off = 1024; lstride = (size_t)3072*1024; tt = tile - 1024; }
    else if (tile < 3072) { W = wv; T = qkvt; K = 1024; N = 1024;
                            row_off = 2048; lstride = (size_t)3072*1024; tt = tile - 2048; }
    else if (tile < 4096) { W = wo; T = wot;  K = 1024; N = 1024;
                            row_off = 0;    lstride = (size_t)1024*1024; tt = tile - 3072; }
    else if (tile < 8192) { W = w1; T = w1t;  K = 1024; N = 4096;
                            row_off = 0;    lstride = (size_t)4096*1024; tt = tile - 4096; }
    else                  { W = w2; T = w2t;  K = 4096; N = 1024;
                            row_off = 0;    lstride = (size_t)4096*1024; tt = tile - 8192; }

    const int ntiles = N >> 5;
    const int n0 = (tt % ntiles) * 32, k0 = (tt / ntiles) * 32;
    const float* Wl = W + (size_t)layer * K * N;
    const int tx = threadIdx.x, ty = threadIdx.y;
#pragma unroll
    for (int i = ty; i < 32; i += 8)
        t[i][tx] = Wl[(size_t)(k0 + i) * N + n0 + tx];
    __syncthreads();
#pragma unroll
    for (int i = ty; i < 32; i += 8) {
        size_t o = (size_t)layer * lstride +
                   (size_t)(row_off + n0 + i) * K + k0 + tx;
        T[o] = __float2half(t[tx][i]);
    }
}

__global__ void concat_bias_kernel(const float* __restrict__ bq,
                                   const float* __restrict__ bk,
                                   const float* __restrict__ bv,
                                   float* __restrict__ dst) {
    int l = blockIdx.y;
    int i = blockIdx.x * 256 + threadIdx.x;   // 0..3071
    float v;
    if (i < 1024) v = bq[l * 1024 + i];
    else if (i < 2048) v = bk[l * 1024 + i - 1024];
    else v = bv[l * 1024 + i - 2048];
    dst[l * 3072 + i] = v;
}

// ---------------- mma.sync fp16 GEMM, fp32 accumulate (QKV / O-proj) --------
#define S_AH 0
#define S_AL 8192
#define S_B  16384
#define S_STG 24576
#define GEMM_SMEM_BYTES (3 * S_STG)   // 73728

__global__ __launch_bounds__(256, 2)
void gemm_tc(const __half* __restrict__ Ah,
             const __half* __restrict__ Al,
             const __half* __restrict__ B,
             const float* __restrict__ bias,
             float* __restrict__ C,
             __half* __restrict__ Hout,
             __half* __restrict__ Lout,
             int M, int N, int K, int relu, int outmode, int use_alo) {
    extern __shared__ char sm[];
    const uint32_t sb = smem_u32(sm);

    const int tid = threadIdx.x;
    const int l = tid & 31, w = tid >> 5;
    const int wm = w & 3, wn = w >> 2;
    const int m0 = blockIdx.y * 128, n0 = blockIdx.x * 128;

    const int lr = tid >> 1;
    const int lkc = (tid & 1) * 2;
    const uint32_t off0 = lr * 64 + ((lkc ^ ((lr >> 1) & 3)) << 4);
    const uint32_t off1 = off0 ^ 16;

    const __half* agh = Ah + (size_t)(m0 + lr) * K + lkc * 8;
    const __half* agl = Al + (size_t)(m0 + lr) * K + lkc * 8;
    const __half* bg  = B  + (size_t)(n0 + lr) * K + lkc * 8;

    auto issue = [&](int c) {
        const uint32_t o = sb + (c % 3) * S_STG;
        const size_t go = (size_t)c * 32;
        cp16(o + S_AH + off0, agh + go);
        cp16(o + S_AH + off1, agh + go + 8);
        if (use_alo) {
            cp16(o + S_AL + off0, agl + go);
            cp16(o + S_AL + off1, agl + go + 8);
        }
        cp16(o + S_B  + off0, bg + go);
        cp16(o + S_B  + off1, bg + go + 8);
        asm volatile("cp.async.commit_group;" ::: "memory");
    };

    float acc[2][8][4] = {};

    const int NCk = K >> 5;
    issue(0);
    issue(1);

    const int ar_l = l & 15;
    const int a_ch = l >> 4;
    const int br_l = ((l >> 4) << 3) + (l & 7);
    const int b_ch = (l >> 3) & 1;

    for (int c = 0; c < NCk; c++) {
        if (c + 1 < NCk) {
            asm volatile("cp.async.wait_group 1;" ::: "memory");
        } else {
            asm volatile("cp.async.wait_group 0;" ::: "memory");
        }
        __syncthreads();
        if (c + 2 < NCk) issue(c + 2);

        const uint32_t o = sb + (c % 3) * S_STG;
#pragma unroll
        for (int ks = 0; ks < 2; ks++) {
            uint32_t ah[2][4], al_[2][4];
#pragma unroll
            for (int mi = 0; mi < 2; mi++) {
                const int ar = wm * 32 + mi * 16 + ar_l;
                const uint32_t aoff =
                    ar * 64 + (((2 * ks + a_ch) ^ ((ar >> 1) & 3)) << 4);
                ldsm4(ah[mi],  o + S_AH + aoff);
                if (use_alo) ldsm4(al_[mi], o + S_AL + aoff);
            }
#pragma unroll
            for (int njq = 0; njq < 8; njq += 4) {
                uint32_t b4[8];
                {
                    const int br0 = wn * 64 + njq * 8 + br_l;
                    const uint32_t bo0 =
                        br0 * 64 + (((2 * ks + b_ch) ^ ((br0 >> 1) & 3)) << 4);
                    ldsm4(b4,     o + S_B + bo0);
                    const int br1 = wn * 64 + (njq + 2) * 8 + br_l;
                    const uint32_t bo1 =
                        br1 * 64 + (((2 * ks + b_ch) ^ ((br1 >> 1) & 3)) << 4);
                    ldsm4(b4 + 4, o + S_B + bo1);
                }
#pragma unroll
                for (int mi = 0; mi < 2; mi++)
#pragma unroll
                    for (int j = 0; j < 4; j++)
                        mma16816(acc[mi][njq + j], ah[mi],
                                 &b4[(j >> 1) * 4 + (j & 1) * 2]);
                if (use_alo) {
#pragma unroll
                    for (int mi = 0; mi < 2; mi++)
#pragma unroll
                        for (int j = 0; j < 4; j++)
                            mma16816(acc[mi][njq + j], al_[mi],
                                     &b4[(j >> 1) * 4 + (j & 1) * 2]);
                }
            }
        }
    }

    const int gid = l >> 2, tig = l & 3;
#pragma unroll
    for (int mi = 0; mi < 2; mi++) {
        const int row0 = m0 + wm * 32 + mi * 16 + gid;
#pragma unroll
        for (int ni = 0; ni < 8; ni++) {
            const int col = n0 + wn * 64 + ni * 8 + tig * 2;
            float b0 = bias[col], b1 = bias[col + 1];
            float v0 = acc[mi][ni][0] + b0;
            float v1 = acc[mi][ni][1] + b1;
            float v2 = acc[mi][ni][2] + b0;
            float v3 = acc[mi][ni][3] + b1;
            if (relu) {
                v0 = fmaxf(v0, 0.0f); v1 = fmaxf(v1, 0.0f);
                v2 = fmaxf(v2, 0.0f); v3 = fmaxf(v3, 0.0f);
            }
            if (outmode == 0) {
                float2 p0 = {v0, v1}, p1 = {v2, v3};
                *(float2*)(C + (size_t)row0 * N + col) = p0;
                *(float2*)(C + (size_t)(row0 + 8) * N + col) = p1;
            } else {
                uint32_t h0, l0u, h1, l1u;
                split2_h(v0, v1, h0, l0u);
                split2_h(v2, v3, h1, l1u);
                *(uint32_t*)(Hout + (size_t)row0 * N + col) = h0;
                *(uint32_t*)(Lout + (size_t)row0 * N + col) = l0u;
                *(uint32_t*)(Hout + (size_t)(row0 + 8) * N + col) = h1;
                *(uint32_t*)(Lout + (size_t)(row0 + 8) * N + col) = l1u;
            }
        }
    }
}

// ---------------- mma.sync fp16 GEMM, f16 accumulate per chunk (FFN) --------
// acc_f16 within each BK=32 chunk, promoted to fp32 once per chunk.
#define H_AH 0
#define H_B  8192
#define H_STG 16384
#define GEMMH_SMEM_BYTES (3 * H_STG)   // 49152

__global__ __launch_bounds__(256, 2)
void gemm_tc_h(const __half* __restrict__ Ah,
               const __half* __restrict__ B,
               const float* __restrict__ bias,
               float* __restrict__ C,
               __half* __restrict__ Hout,
               int M, int N, int K, int relu, int outmode) {
    extern __shared__ char sm[];
    const uint32_t sb = smem_u32(sm);

    const int tid = threadIdx.x;
    const int l = tid & 31, w = tid >> 5;
    const int wm = w & 3, wn = w >> 2;
    const int m0 = blockIdx.y * 128, n0 = blockIdx.x * 128;

    const int lr = tid >> 1;
    const int lkc = (tid & 1) * 2;
    const uint32_t off0 = lr * 64 + ((lkc ^ ((lr >> 1) & 3)) << 4);
    const uint32_t off1 = off0 ^ 16;

    const __half* agh = Ah + (size_t)(m0 + lr) * K + lkc * 8;
    const __half* bg  = B  + (size_t)(n0 + lr) * K + lkc * 8;

    auto issue = [&](int c) {
        const uint32_t o = sb + (c % 3) * H_STG;
        const size_t go = (size_t)c * 32;
        cp16(o + H_AH + off0, agh + go);
        cp16(o + H_AH + off1, agh + go + 8);
        cp16(o + H_B  + off0, bg + go);
        cp16(o + H_B  + off1, bg + go + 8);
        asm volatile("cp.async.commit_group;" ::: "memory");
    };

    float acc[2][8][4] = {};

    const int NCk = K >> 5;
    issue(0);
    issue(1);

    const int ar_l = l & 15;
    const int a_ch = l >> 4;
    const int br_l = ((l >> 4) << 3) + (l & 7);
    const int b_ch = (l >> 3) & 1;

    for (int c = 0; c < NCk; c++) {
        if (c + 1 < NCk) {
            asm volatile("cp.async.wait_group 1;" ::: "memory");
        } else {
            asm volatile("cp.async.wait_group 0;" ::: "memory");
        }
        __syncthreads();
        if (c + 2 < NCk) issue(c + 2);

        const uint32_t o = sb + (c % 3) * H_STG;
        uint32_t hacc[2][8][2];
#pragma unroll
        for (int mi = 0; mi < 2; mi++)
#pragma unroll
            for (int nj = 0; nj < 8; nj++) {
                hacc[mi][nj][0] = 0u; hacc[mi][nj][1] = 0u;
            }

#pragma unroll
        for (int ks = 0; ks < 2; ks++) {
            uint32_t ah[2][4];
#pragma unroll
            for (int mi = 0; mi < 2; mi++) {
                const int ar = wm * 32 + mi * 16 + ar_l;
                const uint32_t aoff =
                    ar * 64 + (((2 * ks + a_ch) ^ ((ar >> 1) & 3)) << 4);
                ldsm4(ah[mi], o + H_AH + aoff);
            }
#pragma unroll
            for (int njq = 0; njq < 8; njq += 4) {
                uint32_t b4[8];
                {
                    const int br0 = wn * 64 + njq * 8 + br_l;
                    const uint32_t bo0 =
                        br0 * 64 + (((2 * ks + b_ch) ^ ((br0 >> 1) & 3)) << 4);
                    ldsm4(b4,     o + H_B + bo0);
                    const int br1 = wn * 64 + (njq + 2) * 8 + br_l;
                    const uint32_t bo1 =
                        br1 * 64 + (((2 * ks + b_ch) ^ ((br1 >> 1) & 3)) << 4);
                    ldsm4(b4 + 4, o + H_B + bo1);
                }
#pragma unroll
                for (int mi = 0; mi < 2; mi++)
#pragma unroll
                    for (int j = 0; j < 4; j++)
                        mma16816_h(hacc[mi][njq + j], ah[mi],
                                   &b4[(j >> 1) * 4 + (j & 1) * 2]);
            }
        }

        // promote chunk partials to fp32
#pragma unroll
        for (int mi = 0; mi < 2; mi++)
#pragma unroll
            for (int nj = 0; nj < 8; nj++) {
                float2 f0 = __half22float2(
                    *reinterpret_cast<__half2*>(&hacc[mi][nj][0]));
                float2 f1 = __half22float2(
                    *reinterpret_cast<__half2*>(&hacc[mi][nj][1]));
                acc[mi][nj][0] += f0.x;
                acc[mi][nj][1] += f0.y;
                acc[mi][nj][2] += f1.x;
                acc[mi][nj][3] += f1.y;
            }
    }

    const int gid = l >> 2, tig = l & 3;
#pragma unroll
    for (int mi = 0; mi < 2; mi++) {
        const int row0 = m0 + wm * 32 + mi * 16 + gid;
#pragma unroll
        for (int ni = 0; ni < 8; ni++) {
            const int col = n0 + wn * 64 + ni * 8 + tig * 2;
            float b0 = bias[col], b1 = bias[col + 1];
            float v0 = acc[mi][ni][0] + b0;
            float v1 = acc[mi][ni][1] + b1;
            float v2 = acc[mi][ni][2] + b0;
            float v3 = acc[mi][ni][3] + b1;
            if (relu) {
                v0 = fmaxf(v0, 0.0f); v1 = fmaxf(v1, 0.0f);
                v2 = fmaxf(v2, 0.0f); v3 = fmaxf(v3, 0.0f);
            }
            if (outmode == 0) {
                float2 p0 = {v0, v1}, p1 = {v2, v3};
                *(float2*)(C + (size_t)row0 * N + col) = p0;
                *(float2*)(C + (size_t)(row0 + 8) * N + col) = p1;
            } else {
                __half2 h0 = __floats2half2_rn(v0, v1);
                __half2 h1 = __floats2half2_rn(v2, v3);
                *(__half2*)(Hout + (size_t)row0 * N + col) = h0;
                *(__half2*)(Hout + (size_t)(row0 + 8) * N + col) = h1;
            }
        }
    }
}

// ---------------- embedding + PE, fused fp16 split ---------------------------
__global__ __launch_bounds__(256)
void embed_kernel(const int* __restrict__ src,
                  const float* __restrict__ emb,
                  const float* __restrict__ pe,
                  float* __restrict__ x,
                  __half* __restrict__ H,
                  __half* __restrict__ L) {
    int row = blockIdx.x;
    int s = row & (SEQ - 1);
    int tok = src[row];
    int c = threadIdx.x * 4;
    const float* erow = emb + (size_t)tok * D_MODEL;
    const float* prow = pe + (size_t)s * D_MODEL;
    float4 e = *(const float4*)(erow + c);
    float4 p = *(const float4*)(prow + c);
    float4 v;
    v.x = e.x * 32.0f + p.x; v.y = e.y * 32.0f + p.y;
    v.z = e.z * 32.0f + p.z; v.w = e.w * 32.0f + p.w;
    size_t idx = (size_t)row * D_MODEL + c;
    *(float4*)(x + idx) = v;
    store_split4(H, L, idx, v);
}

// ---------------- tensor-core flash attention (unchanged from R12) ----------
#define AT_QH 0
#define AT_QL 8192
#define AT_KH 16384
#define AT_VTH 24576
#define AT_VTL 32768
#define AT_MS 40960
#define ATT_SMEM_BYTES (40960 + 256)
#define QKV_N 3072

__device__ __forceinline__ uint32_t swz128(int row, int ch) {
    return (uint32_t)(row * 128 + ((ch ^ (row & 7)) << 4));
}

__global__ __launch_bounds__(128)
void attn_mma_kernel(const __half* __restrict__ QKVh,
                     const __half* __restrict__ QKVl,
                     const int* __restrict__ mask,
                     __half* __restrict__ Oh,
                     __half* __restrict__ Ol) {
    extern __shared__ char sm[];
    const uint32_t sb = smem_u32(sm);
    int* ms = (int*)(sm + AT_MS);

    const int tid = threadIdx.x;
    const int l = tid & 31, w = tid >> 5;
    const int gid = l >> 2, tig = l & 3;
    const int qt = blockIdx.x, h = blockIdx.y, b = blockIdx.z;
    const size_t brow = (size_t)b * SEQ;

    {
        const int row = tid >> 1;
        const size_t g = (brow + qt * 64 + row) * QKV_N + h * 64;
#pragma unroll
        for (int i = 0; i < 4; i++) {
            const int ch = (tid & 1) * 4 + i;
            cp16(sb + AT_QH + swz128(row, ch), QKVh + g + ch * 8);
            cp16(sb + AT_QL + swz128(row, ch), QKVl + g + ch * 8);
        }
        asm volatile("cp.async.commit_group;" ::: "memory");
    }

    float m0 = -1e30f, m1 = -1e30f, lsum0 = 0.0f, lsum1 = 0.0f;
    float O[8][4] = {};

    const int ar_l = l & 15;
    const int a_ch = l >> 4;
    const int br_l = ((l >> 4) << 3) + (l & 7);
    const int b_ch = (l >> 3) & 1;

    for (int kt = 0; kt < SEQ / 64; kt++) {
        __syncthreads();
        {
            const int row = tid >> 1;
            const size_t g = (brow + kt * 64 + row) * QKV_N + 1024 + h * 64;
#pragma unroll
            for (int i = 0; i < 4; i++) {
                const int ch = (tid & 1) * 4 + i;
                cp16(sb + AT_KH + swz128(row, ch), QKVh + g + ch * 8);
            }
            asm volatile("cp.async.commit_group;" ::: "memory");
        }
        {
            const int kr = tid >> 1;
            const size_t g = (brow + kt * 64 + kr) * QKV_N + 2048 + h * 64;
#pragma unroll
            for (int i = 0; i < 4; i++) {
                const int dg = (tid & 1) * 4 + i;
                union { uint4 u; __half hx[8]; } vh, vl;
                vh.u = *(const uint4*)(QKVh + g + dg * 8);
                vl.u = *(const uint4*)(QKVl + g + dg * 8);
#pragma unroll
                for (int jj = 0; jj < 8; jj++) {
                    const int d = dg * 8 + jj;
                    const uint32_t o = (uint32_t)(d * 128 +
                        (((kr >> 3) ^ (d & 7)) << 4) + (kr & 7) * 2);
                    *(__half*)(sm + AT_VTH + o) = vh.hx[jj];
                    *(__half*)(sm + AT_VTL + o) = vl.hx[jj];
                }
            }
        }
        if (tid < 64) ms[tid] = mask[b * SEQ + kt * 64 + tid];
        asm volatile("cp.async.wait_group 0;" ::: "memory");
        __syncthreads();

        float s[8][4] = {};
#pragma unroll
        for (int dk = 0; dk < 4; dk++) {
            uint32_t qh[4], ql[4];
            const int arow = w * 16 + ar_l;
            const uint32_t aoff = swz128(arow, 2 * dk + a_ch);
            ldsm4(qh, sb + AT_QH + aoff);
            ldsm4(ql, sb + AT_QL + aoff);
#pragma unroll
            for (int bj = 0; bj < 4; bj++) {
                uint32_t kb[4];
                const int krow = bj * 16 + br_l;
                ldsm4(kb, sb + AT_KH + swz128(krow, 2 * dk + b_ch));
                mma16816(s[2 * bj],     qh, kb);
                mma16816(s[2 * bj + 1], qh, kb + 2);
                mma16816(s[2 * bj],     ql, kb);
                mma16816(s[2 * bj + 1], ql, kb + 2);
            }
        }

        float rm0 = -1e30f, rm1 = -1e30f;
#pragma unroll
        for (int j = 0; j < 8; j++) {
            const int col = j * 8 + 2 * tig;
            const int k0 = ms[col], k1 = ms[col + 1];
            s[j][0] = k0 ? s[j][0] * 0.125f : -1e9f;
            s[j][1] = k1 ? s[j][1] * 0.125f : -1e9f;
            s[j][2] = k0 ? s[j][2] * 0.125f : -1e9f;
            s[j][3] = k1 ? s[j][3] * 0.125f : -1e9f;
            rm0 = fmaxf(rm0, fmaxf(s[j][0], s[j][1]));
            rm1 = fmaxf(rm1, fmaxf(s[j][2], s[j][3]));
        }
        rm0 = fmaxf(rm0, __shfl_xor_sync(0xffffffffu, rm0, 1));
        rm0 = fmaxf(rm0, __shfl_xor_sync(0xffffffffu, rm0, 2));
        rm1 = fmaxf(rm1, __shfl_xor_sync(0xffffffffu, rm1, 1));
        rm1 = fmaxf(rm1, __shfl_xor_sync(0xffffffffu, rm1, 2));

        const float mn0 = fmaxf(m0, rm0), mn1 = fmaxf(m1, rm1);
        const float sc0 = __expf(m0 - mn0), sc1 = __expf(m1 - mn1);
        m0 = mn0; m1 = mn1;

        float ps0 = 0.0f, ps1 = 0.0f;
#pragma unroll
        for (int j = 0; j < 8; j++) {
            s[j][0] = __expf(s[j][0] - mn0);
            s[j][1] = __expf(s[j][1] - mn0);
            s[j][2] = __expf(s[j][2] - mn1);
            s[j][3] = __expf(s[j][3] - mn1);
            ps0 += s[j][0] + s[j][1];
            ps1 += s[j][2] + s[j][3];
        }
        ps0 += __shfl_xor_sync(0xffffffffu, ps0, 1);
        ps0 += __shfl_xor_sync(0xffffffffu, ps0, 2);
        ps1 += __shfl_xor_sync(0xffffffffu, ps1, 1);
        ps1 += __shfl_xor_sync(0xffffffffu, ps1, 2);
        lsum0 = lsum0 * sc0 + ps0;
        lsum1 = lsum1 * sc1 + ps1;

#pragma unroll
        for (int dt = 0; dt < 8; dt++) {
            O[dt][0] *= sc0; O[dt][1] *= sc0;
            O[dt][2] *= sc1; O[dt][3] *= sc1;
        }

#pragma unroll
        for (int kk = 0; kk < 4; kk++) {
            uint32_t pah[4], pal[4];
            split2_h(s[2 * kk][0],     s[2 * kk][1],     pah[0], pal[0]);
            split2_h(s[2 * kk][2],     s[2 * kk][3],     pah[1], pal[1]);
            split2_h(s[2 * kk + 1][0], s[2 * kk + 1][1], pah[2], pal[2]);
            split2_h(s[2 * kk + 1][2], s[2 * kk + 1][3], pah[3], pal[3]);
#pragma unroll
            for (int dg = 0; dg < 4; dg++) {
                uint32_t bh[4], bl[4];
                const int drow = dg * 16 + br_l;
                const uint32_t bo = swz128(drow, 2 * kk + b_ch);
                ldsm4(bh, sb + AT_VTH + bo);
                ldsm4(bl, sb + AT_VTL + bo);
                mma16816(O[2 * dg],     pah, bh);
                mma16816(O[2 * dg + 1], pah, bh + 2);
                mma16816(O[2 * dg],     pah, bl);
                mma16816(O[2 * dg + 1], pah, bl + 2);
                mma16816(O[2 * dg],     pal, bh);
                mma16816(O[2 * dg + 1], pal, bh + 2);
            }
        }
    }

    const float inv0 = 1.0f / lsum0, inv1 = 1.0f / lsum1;
    const size_t row0 = brow + qt * 64 + w * 16 + gid;
    const size_t row1 = row0 + 8;
#pragma unroll
    for (int dt = 0; dt < 8; dt++) {
        const int col = h * 64 + dt * 8 + 2 * tig;
        uint32_t h0, l0u, h1, l1u;
        split2_h(O[dt][0] * inv0, O[dt][1] * inv0, h0, l0u);
        split2_h(O[dt][2] * inv1, O[dt][3] * inv1, h1, l1u);
        *(uint32_t*)(Oh + row0 * D_MODEL + col) = h0;
        *(uint32_t*)(Ol + row0 * D_MODEL + col) = l0u;
        *(uint32_t*)(Oh + row1 * D_MODEL + col) = h1;
        *(uint32_t*)(Ol + row1 * D_MODEL + col) = l1u;
    }
}

// ---------------- fused residual add + LayerNorm + optional fp16 split ------
__global__ __launch_bounds__(256)
void add_ln_kernel(const float* __restrict__ x,
                   const float* __restrict__ r,
                   const float* __restrict__ g,
                   const float* __restrict__ bta,
                   float* __restrict__ y,
                   __half* __restrict__ H,
                   __half* __restrict__ L,
                   int write_split) {
    const int row = blockIdx.x;
    const int tid = threadIdx.x;
    const int c = tid * 4;
    const size_t idx = (size_t)row * D_MODEL + c;

    float4 xv = *(const float4*)(x + idx);
    float4 rv = *(const float4*)(r + idx);
    float4 v;
    v.x = xv.x + rv.x; v.y = xv.y + rv.y;
    v.z = xv.z + rv.z; v.w = xv.w + rv.w;

    float s = v.x + v.y + v.z + v.w;
    float ss = fmaf(v.x, v.x, fmaf(v.y, v.y, fmaf(v.z, v.z, v.w * v.w)));

    __shared__ float rs[256], rss[256];
    rs[tid] = s; rss[tid] = ss;
    __syncthreads();
    for (int off = 128; off > 0; off >>= 1) {
        if (tid < off) { rs[tid] += rs[tid + off]; rss[tid] += rss[tid + off]; }
        __syncthreads();
    }
    float mean = rs[0] * (1.0f / D_MODEL);
    float var = rss[0] * (1.0f / D_MODEL) - mean * mean;
    float inv = rsqrtf(var + 1e-5f);

    float4 gg = *(const float4*)(g + c);
    float4 bb = *(const float4*)(bta + c);
    float4 o;
    o.x = (v.x - mean) * inv * gg.x + bb.x;
    o.y = (v.y - mean) * inv * gg.y + bb.y;
    o.z = (v.z - mean) * inv * gg.z + bb.z;
    o.w = (v.w - mean) * inv * gg.w + bb.w;
    *(float4*)(y + idx) = o;
    if (write_split) store_split4(H, L, idx, o);
}

// ---------------- host orchestration ---------------------------------------
extern "C" void kernel_launch(void* const* d_in, const int* in_sizes, int n_in,
                              void* d_out, int out_size) {
    const int*   src  = (const int*)d_in[0];
    const int*   mask = (const int*)d_in[1];
    const float* emb  = (const float*)d_in[2];
    const float* pe   = (const float*)d_in[3];
    const float* wq = (const float*)d_in[4];
    const float* bq = (const float*)d_in[5];
    const float* wk = (const float*)d_in[6];
    const float* bk = (const float*)d_in[7];
    const float* wv = (const float*)d_in[8];
    const float* bv = (const float*)d_in[9];
    const float* wo = (const float*)d_in[10];
    const float* bo = (const float*)d_in[11];
    const float* w1 = (const float*)d_in[12];
    const float* b1 = (const float*)d_in[13];
    const float* w2 = (const float*)d_in[14];
    const float* b2 = (const float*)d_in[15];
    const float* g1  = (const float*)d_in[16];
    const float* be1 = (const float*)d_in[17];
    const float* g2  = (const float*)d_in[18];
    const float* be2 = (const float*)d_in[19];
    float* out = (float*)d_out;

    float *px, *pt, *pbqkv;
    cudaGetSymbolAddress((void**)&px, g_x);
    cudaGetSymbolAddress((void**)&pt, g_t);
    cudaGetSymbolAddress((void**)&pbqkv, g_bqkv);

    __half *qkvh, *qkvl, *ah, *al, *hh;
    cudaGetSymbolAddress((void**)&qkvh, g_qkvh);
    cudaGetSymbolAddress((void**)&qkvl, g_qkvl);
    cudaGetSymbolAddress((void**)&ah, g_ah);
    cudaGetSymbolAddress((void**)&al, g_al);
    cudaGetSymbolAddress((void**)&hh, g_hh);

    __half *wqkvt, *wot, *w1t, *w2t;
    cudaGetSymbolAddress((void**)&wqkvt, g_wqkvt);
    cudaGetSymbolAddress((void**)&wot, g_wot);
    cudaGetSymbolAddress((void**)&w1t, g_w1t);
    cudaGetSymbolAddress((void**)&w2t, g_w2t);

    static int attr_set = 0;
    if (!attr_set) {
        cudaFuncSetAttribute(gemm_tc, cudaFuncAttributeMaxDynamicSharedMemorySize,
                             GEMM_SMEM_BYTES);
        cudaFuncSetAttribute(gemm_tc_h, cudaFuncAttributeMaxDynamicSharedMemorySize,
                             GEMMH_SMEM_BYTES);
        cudaFuncSetAttribute(attn_mma_kernel,
                             cudaFuncAttributeMaxDynamicSharedMemorySize,
                             ATT_SMEM_BYTES);
        attr_set = 1;
    }

    // ---- weight prep: ONE launch ----
    prep_weights_kernel<<<dim3(12288, 1, 6), dim3(32, 8)>>>(
        wq, wk, wv, wo, w1, w2, wqkvt, wot, w1t, w2t);
    concat_bias_kernel<<<dim3(12, 6), 256>>>(bq, bk, bv, pbqkv);

    embed_kernel<<<ROWS, 256>>>(src, emb, pe, px, ah, al);

    dim3 g_qkv_grid(3072 / 128, ROWS / 128);   // (24, 32)
    dim3 g_dd(D_MODEL / 128, ROWS / 128);      // (8, 32)
    dim3 g_ff(D_FF / 128,    ROWS / 128);      // (32, 32)
    dim3 attn_grid(SEQ / 64, N_HEADS, BATCH);

    for (int l = 0; l < N_LAYERS; l++) {
        size_t woqkv = (size_t)l * 3072 * 1024;
        size_t wofs  = (size_t)l * 1024 * 1024;
        size_t bofs  = (size_t)l * D_MODEL;
        size_t wfofs = (size_t)l * 4096 * 1024;
        size_t b1ofs = (size_t)l * D_FF;

        // QKV projection (split-2 A, f32 acc) -> fp16 hi/lo
        gemm_tc<<<g_qkv_grid, 256, GEMM_SMEM_BYTES>>>(
            ah, al, wqkvt + woqkv, pbqkv + l * 3072,
            nullptr, qkvh, qkvl, ROWS, 3072, 1024, 0, 1, 1);

        // tensor-core flash attention -> fp16 hi/lo (O-proj input)
        attn_mma_kernel<<<attn_grid, 128, ATT_SMEM_BYTES>>>(
            qkvh, qkvl, mask, ah, al);

        // O projection (split-2 A, f32 acc) -> fp32
        gemm_tc<<<g_dd, 256, GEMM_SMEM_BYTES>>>(
            ah, al, wot + wofs, bo + bofs,
            pt, nullptr, nullptr, ROWS, 1024, 1024, 0, 0, 1);

        add_ln_kernel<<<ROWS, 256>>>(px, pt, g1 + bofs, be1 + bofs, px, ah, al, 1);

        // FFN1: f16-accumulate (per-chunk f32 promote), relu, fp16-hi out
        gemm_tc_h<<<g_ff, 256, GEMMH_SMEM_BYTES>>>(
            ah, w1t + wfofs, b1 + b1ofs,
            nullptr, hh, ROWS, 4096, 1024, 1, 1);

        // FFN2: f16-accumulate -> fp32
        gemm_tc_h<<<g_dd, 256, GEMMH_SMEM_BYTES>>>(
            hh, w2t + wfofs, b2 + bofs,
            pt, nullptr, ROWS, 1024, 4096, 0, 0);

        if (l == N_LAYERS - 1) {
            add_ln_kernel<<<ROWS, 256>>>(px, pt, g2 + bofs, be2 + bofs, out,
                                         ah, al, 0);
        } else {
            add_ln_kernel<<<ROWS, 256>>>(px, pt, g2 + bofs, be2 + bofs, px,
                                         ah, al, 1);
        }
    }
}

// round 15
// speedup vs baseline: 1.1327x; 1.1327x over previous
#include <cuda_runtime.h>
#include <cuda_fp16.h>
#include <math.h>
#include <stdint.h>

#define D_MODEL 1024
#define N_HEADS 16
#define D_K 64
#define D_FF 4096
#define N_LAYERS 6
#define BATCH 4
#define SEQ 1024
#define ROWS (BATCH * SEQ)   // 4096

// ---------------- scratch (device globals; no allocation allowed) ----------
__device__ float g_x[ROWS * D_MODEL];                 // residual stream (fp32)
__device__ float g_t[ROWS * D_MODEL];                 // pre-LN gemm output
__device__ __half g_qkvh[(size_t)ROWS * 3 * D_MODEL]; // QKV fp16 hi
__device__ __half g_qkvl[(size_t)ROWS * 3 * D_MODEL]; // QKV fp16 lo
__device__ __half g_ah[(size_t)ROWS * D_MODEL];       // activation hi
__device__ __half g_al[(size_t)ROWS * D_MODEL];       // activation lo
__device__ __half g_hh[(size_t)ROWS * D_FF];          // ffn hidden hi

// transposed weights: [N,K] K-major fp16
__device__ __half g_wqkvt[6u*3072*1024];
__device__ __half g_wot[6u*1024*1024];
__device__ __half g_w1t[6u*4096*1024];
__device__ __half g_w2t[6u*4096*1024];
__device__ float g_bqkv[6 * 3072];

// ---------------- PTX helpers ------------------------------------------------
__device__ __forceinline__ uint32_t smem_u32(const void* p) {
    uint32_t a;
    asm("{ .reg .u64 t; cvta.to.shared.u64 t, %1; cvt.u32.u64 %0, t; }"
        : "=r"(a) : "l"(p));
    return a;
}

__device__ __forceinline__ void cp16(uint32_t s, const void* g) {
    asm volatile("cp.async.cg.shared.global [%0], [%1], 16;"
                 :: "r"(s), "l"(g) : "memory");
}

__device__ __forceinline__ void ldsm4(uint32_t* r, uint32_t addr) {
    asm volatile("ldmatrix.sync.aligned.m8n8.x4.shared.b16 {%0,%1,%2,%3}, [%4];"
                 : "=r"(r[0]), "=r"(r[1]), "=r"(r[2]), "=r"(r[3]) : "r"(addr));
}

__device__ __forceinline__ void mma16816(float* c, const uint32_t* a,
                                         const uint32_t* b) {
    asm volatile(
        "mma.sync.aligned.m16n8k16.row.col.f32.f16.f16.f32 "
        "{%0,%1,%2,%3}, {%4,%5,%6,%7}, {%8,%9}, {%0,%1,%2,%3};"
        : "+f"(c[0]), "+f"(c[1]), "+f"(c[2]), "+f"(c[3])
        : "r"(a[0]), "r"(a[1]), "r"(a[2]), "r"(a[3]), "r"(b[0]), "r"(b[1]));
}

// split a float4 into fp16 hi/lo pairs, store 8B each
__device__ __forceinline__ void store_split4(__half* H, __half* L,
                                             size_t idx, float4 v) {
    __half2 h0 = __floats2half2_rn(v.x, v.y);
    __half2 h1 = __floats2half2_rn(v.z, v.w);
    float2 f0 = __half22float2(h0);
    float2 f1 = __half22float2(h1);
    __half2 l0 = __floats2half2_rn(v.x - f0.x, v.y - f0.y);
    __half2 l1 = __floats2half2_rn(v.z - f1.x, v.w - f1.y);
    uint2 hh, ll;
    hh.x = *reinterpret_cast<uint32_t*>(&h0);
    hh.y = *reinterpret_cast<uint32_t*>(&h1);
    ll.x = *reinterpret_cast<uint32_t*>(&l0);
    ll.y = *reinterpret_cast<uint32_t*>(&l1);
    *(uint2*)(H + idx) = hh;
    *(uint2*)(L + idx) = ll;
}

// split 2 floats into fp16 hi/lo half2 (as uint32)
__device__ __forceinline__ void split2_h(float a, float b,
                                         uint32_t& hi, uint32_t& lo) {
    __half2 h = __floats2half2_rn(a, b);
    float2 f = __half22float2(h);
    __half2 l = __floats2half2_rn(a - f.x, b - f.y);
    hi = *reinterpret_cast<uint32_t*>(&h);
    lo = *reinterpret_cast<uint32_t*>(&l);
}

// ---------------- single-launch weight prep (transpose + fp16 convert) ------
__global__ void prep_weights_kernel(
    const float* __restrict__ wq, const float* __restrict__ wk,
    const float* __restrict__ wv, const float* __restrict__ wo,
    const float* __restrict__ w1, const float* __restrict__ w2,
    __half* __restrict__ qkvt, __half* __restrict__ wot,
    __half* __restrict__ w1t,  __half* __restrict__ w2t) {
    __shared__ float t[32][33];
    const int tile = blockIdx.x;       // 0..12287
    const int layer = blockIdx.z;

    const float* W; __half* T;
    int K, N, row_off, tt; size_t lstride;
    if (tile < 1024)      { W = wq; T = qkvt; K = 1024; N = 1024;
                            row_off = 0;    lstride = (size_t)3072*1024; tt = tile; }
    else if (tile < 2048) { W = wk; T = qkvt; K = 1024; N = 1024;
                            row_off = 1024; lstride = (size_t)3072*1024; tt = tile - 1024; }
    else if (tile < 3072) { W = wv; T = qkvt; K = 1024; N = 1024;
                            row_off = 2048; lstride = (size_t)3072*1024; tt = tile - 2048; }
    else if (tile < 4096) { W = wo; T = wot;  K = 1024; N = 1024;
                            row_off = 0;    lstride = (size_t)1024*1024; tt = tile - 3072; }
    else if (tile < 8192) { W = w1; T = w1t;  K = 1024; N = 4096;
                            row_off = 0;    lstride = (size_t)4096*1024; tt = tile - 4096; }
    else                  { W = w2; T = w2t;  K = 4096; N = 1024;
                            row_off = 0;    lstride = (size_t)4096*1024; tt = tile - 8192; }

    const int ntiles = N >> 5;
    const int n0 = (tt % ntiles) * 32, k0 = (tt / ntiles) * 32;
    const float* Wl = W + (size_t)layer * K * N;
    const int tx = threadIdx.x, ty = threadIdx.y;
#pragma unroll
    for (int i = ty; i < 32; i += 8)
        t[i][tx] = Wl[(size_t)(k0 + i) * N + n0 + tx];
    __syncthreads();
#pragma unroll
    for (int i = ty; i < 32; i += 8) {
        size_t o = (size_t)layer * lstride +
                   (size_t)(row_off + n0 + i) * K + k0 + tx;
        T[o] = __float2half(t[tx][i]);
    }
}

__global__ void concat_bias_kernel(const float* __restrict__ bq,
                                   const float* __restrict__ bk,
                                   const float* __restrict__ bv,
                                   float* __restrict__ dst) {
    int l = blockIdx.y;
    int i = blockIdx.x * 256 + threadIdx.x;   // 0..3071
    float v;
    if (i < 1024) v = bq[l * 1024 + i];
    else if (i < 2048) v = bk[l * 1024 + i - 1024];
    else v = bv[l * 1024 + i - 2048];
    dst[l * 3072 + i] = v;
}

// ---------------- mma.sync fp16 GEMM, fp32 accumulate, templated ------------
// C[M,N] = (Ah [+ Al])[M,K] @ B[N,K]^T + bias.
// USE_ALO: split-2 A vs single-term. OUTMODE: 0=fp32 C, 1=fp16 hi/lo, 2=fp16 hi.
#define S_AH 0
#define S_AL 8192
#define S_B  16384
#define S_STG 24576
#define GEMM_SMEM_BYTES (3 * S_STG)   // 73728

template <int USE_ALO, int OUTMODE, int RELU>
__global__ __launch_bounds__(256, 2)
void gemm_tc(const __half* __restrict__ Ah,
             const __half* __restrict__ Al,
             const __half* __restrict__ B,
             const float* __restrict__ bias,
             float* __restrict__ C,
             __half* __restrict__ Hout,
             __half* __restrict__ Lout,
             int M, int N, int K) {
    extern __shared__ char sm[];
    const uint32_t sb = smem_u32(sm);

    const int tid = threadIdx.x;
    const int l = tid & 31, w = tid >> 5;
    const int wm = w & 3, wn = w >> 2;
    const int m0 = blockIdx.y * 128, n0 = blockIdx.x * 128;

    const int lr = tid >> 1;
    const int lkc = (tid & 1) * 2;
    const uint32_t off0 = lr * 64 + ((lkc ^ ((lr >> 1) & 3)) << 4);
    const uint32_t off1 = off0 ^ 16;

    const __half* agh = Ah + (size_t)(m0 + lr) * K + lkc * 8;
    const __half* agl = USE_ALO ? Al + (size_t)(m0 + lr) * K + lkc * 8 : nullptr;
    const __half* bg  = B  + (size_t)(n0 + lr) * K + lkc * 8;

    auto issue = [&](int c) {
        const uint32_t o = sb + (c % 3) * S_STG;
        const size_t go = (size_t)c * 32;
        cp16(o + S_AH + off0, agh + go);
        cp16(o + S_AH + off1, agh + go + 8);
        if (USE_ALO) {
            cp16(o + S_AL + off0, agl + go);
            cp16(o + S_AL + off1, agl + go + 8);
        }
        cp16(o + S_B  + off0, bg + go);
        cp16(o + S_B  + off1, bg + go + 8);
        asm volatile("cp.async.commit_group;" ::: "memory");
    };

    float acc[2][8][4] = {};

    const int NCk = K >> 5;
    issue(0);
    issue(1);

    const int ar_l = l & 15;
    const int a_ch = l >> 4;
    const int br_l = ((l >> 4) << 3) + (l & 7);
    const int b_ch = (l >> 3) & 1;

    for (int c = 0; c < NCk; c++) {
        if (c + 1 < NCk) {
            asm volatile("cp.async.wait_group 1;" ::: "memory");
        } else {
            asm volatile("cp.async.wait_group 0;" ::: "memory");
        }
        __syncthreads();
        if (c + 2 < NCk) issue(c + 2);

        const uint32_t o = sb + (c % 3) * S_STG;
#pragma unroll
        for (int ks = 0; ks < 2; ks++) {
            uint32_t ah[2][4], al_[2][4];
#pragma unroll
            for (int mi = 0; mi < 2; mi++) {
                const int ar = wm * 32 + mi * 16 + ar_l;
                const uint32_t aoff =
                    ar * 64 + (((2 * ks + a_ch) ^ ((ar >> 1) & 3)) << 4);
                ldsm4(ah[mi],  o + S_AH + aoff);
                if (USE_ALO) ldsm4(al_[mi], o + S_AL + aoff);
            }
#pragma unroll
            for (int njq = 0; njq < 8; njq += 4) {
                uint32_t b4[8];
                {
                    const int br0 = wn * 64 + njq * 8 + br_l;
                    const uint32_t bo0 =
                        br0 * 64 + (((2 * ks + b_ch) ^ ((br0 >> 1) & 3)) << 4);
                    ldsm4(b4,     o + S_B + bo0);
                    const int br1 = wn * 64 + (njq + 2) * 8 + br_l;
                    const uint32_t bo1 =
                        br1 * 64 + (((2 * ks + b_ch) ^ ((br1 >> 1) & 3)) << 4);
                    ldsm4(b4 + 4, o + S_B + bo1);
                }
#pragma unroll
                for (int mi = 0; mi < 2; mi++)
#pragma unroll
                    for (int j = 0; j < 4; j++)
                        mma16816(acc[mi][njq + j], ah[mi],
                                 &b4[(j >> 1) * 4 + (j & 1) * 2]);
                if (USE_ALO) {
#pragma unroll
                    for (int mi = 0; mi < 2; mi++)
#pragma unroll
                        for (int j = 0; j < 4; j++)
                            mma16816(acc[mi][njq + j], al_[mi],
                                     &b4[(j >> 1) * 4 + (j & 1) * 2]);
                }
            }
        }
    }

    const int gid = l >> 2, tig = l & 3;
#pragma unroll
    for (int mi = 0; mi < 2; mi++) {
        const int row0 = m0 + wm * 32 + mi * 16 + gid;
#pragma unroll
        for (int ni = 0; ni < 8; ni++) {
            const int col = n0 + wn * 64 + ni * 8 + tig * 2;
            float b0 = bias[col], b1 = bias[col + 1];
            float v0 = acc[mi][ni][0] + b0;
            float v1 = acc[mi][ni][1] + b1;
            float v2 = acc[mi][ni][2] + b0;
            float v3 = acc[mi][ni][3] + b1;
            if (RELU) {
                v0 = fmaxf(v0, 0.0f); v1 = fmaxf(v1, 0.0f);
                v2 = fmaxf(v2, 0.0f); v3 = fmaxf(v3, 0.0f);
            }
            if (OUTMODE == 0) {
                float2 p0 = {v0, v1}, p1 = {v2, v3};
                *(float2*)(C + (size_t)row0 * N + col) = p0;
                *(float2*)(C + (size_t)(row0 + 8) * N + col) = p1;
            } else if (OUTMODE == 1) {
                uint32_t h0, l0u, h1, l1u;
                split2_h(v0, v1, h0, l0u);
                split2_h(v2, v3, h1, l1u);
                *(uint32_t*)(Hout + (size_t)row0 * N + col) = h0;
                *(uint32_t*)(Lout + (size_t)row0 * N + col) = l0u;
                *(uint32_t*)(Hout + (size_t)(row0 + 8) * N + col) = h1;
                *(uint32_t*)(Lout + (size_t)(row0 + 8) * N + col) = l1u;
            } else {
                __half2 h0 = __floats2half2_rn(v0, v1);
                __half2 h1 = __floats2half2_rn(v2, v3);
                *(__half2*)(Hout + (size_t)row0 * N + col) = h0;
                *(__half2*)(Hout + (size_t)(row0 + 8) * N + col) = h1;
            }
        }
    }
}

// ---------------- embedding + PE, fused fp16 split ---------------------------
__global__ __launch_bounds__(256)
void embed_kernel(const int* __restrict__ src,
                  const float* __restrict__ emb,
                  const float* __restrict__ pe,
                  float* __restrict__ x,
                  __half* __restrict__ H,
                  __half* __restrict__ L) {
    int row = blockIdx.x;
    int s = row & (SEQ - 1);
    int tok = src[row];
    int c = threadIdx.x * 4;
    const float* erow = emb + (size_t)tok * D_MODEL;
    const float* prow = pe + (size_t)s * D_MODEL;
    float4 e = *(const float4*)(erow + c);
    float4 p = *(const float4*)(prow + c);
    float4 v;
    v.x = e.x * 32.0f + p.x; v.y = e.y * 32.0f + p.y;
    v.z = e.z * 32.0f + p.z; v.w = e.w * 32.0f + p.w;
    size_t idx = (size_t)row * D_MODEL + c;
    *(float4*)(x + idx) = v;
    store_split4(H, L, idx, v);
}

// ---------------- tensor-core flash attention (unchanged from R12) ----------
#define AT_QH 0
#define AT_QL 8192
#define AT_KH 16384
#define AT_VTH 24576
#define AT_VTL 32768
#define AT_MS 40960
#define ATT_SMEM_BYTES (40960 + 256)
#define QKV_N 3072

__device__ __forceinline__ uint32_t swz128(int row, int ch) {
    return (uint32_t)(row * 128 + ((ch ^ (row & 7)) << 4));
}

__global__ __launch_bounds__(128)
void attn_mma_kernel(const __half* __restrict__ QKVh,
                     const __half* __restrict__ QKVl,
                     const int* __restrict__ mask,
                     __half* __restrict__ Oh,
                     __half* __restrict__ Ol) {
    extern __shared__ char sm[];
    const uint32_t sb = smem_u32(sm);
    int* ms = (int*)(sm + AT_MS);

    const int tid = threadIdx.x;
    const int l = tid & 31, w = tid >> 5;
    const int gid = l >> 2, tig = l & 3;
    const int qt = blockIdx.x, h = blockIdx.y, b = blockIdx.z;
    const size_t brow = (size_t)b * SEQ;

    {
        const int row = tid >> 1;
        const size_t g = (brow + qt * 64 + row) * QKV_N + h * 64;
#pragma unroll
        for (int i = 0; i < 4; i++) {
            const int ch = (tid & 1) * 4 + i;
            cp16(sb + AT_QH + swz128(row, ch), QKVh + g + ch * 8);
            cp16(sb + AT_QL + swz128(row, ch), QKVl + g + ch * 8);
        }
        asm volatile("cp.async.commit_group;" ::: "memory");
    }

    float m0 = -1e30f, m1 = -1e30f, lsum0 = 0.0f, lsum1 = 0.0f;
    float O[8][4] = {};

    const int ar_l = l & 15;
    const int a_ch = l >> 4;
    const int br_l = ((l >> 4) << 3) + (l & 7);
    const int b_ch = (l >> 3) & 1;

    for (int kt = 0; kt < SEQ / 64; kt++) {
        __syncthreads();
        {
            const int row = tid >> 1;
            const size_t g = (brow + kt * 64 + row) * QKV_N + 1024 + h * 64;
#pragma unroll
            for (int i = 0; i < 4; i++) {
                const int ch = (tid & 1) * 4 + i;
                cp16(sb + AT_KH + swz128(row, ch), QKVh + g + ch * 8);
            }
            asm volatile("cp.async.commit_group;" ::: "memory");
        }
        {
            const int kr = tid >> 1;
            const size_t g = (brow + kt * 64 + kr) * QKV_N + 2048 + h * 64;
#pragma unroll
            for (int i = 0; i < 4; i++) {
                const int dg = (tid & 1) * 4 + i;
                union { uint4 u; __half hx[8]; } vh, vl;
                vh.u = *(const uint4*)(QKVh + g + dg * 8);
                vl.u = *(const uint4*)(QKVl + g + dg * 8);
#pragma unroll
                for (int jj = 0; jj < 8; jj++) {
                    const int d = dg * 8 + jj;
                    const uint32_t o = (uint32_t)(d * 128 +
                        (((kr >> 3) ^ (d & 7)) << 4) + (kr & 7) * 2);
                    *(__half*)(sm + AT_VTH + o) = vh.hx[jj];
                    *(__half*)(sm + AT_VTL + o) = vl.hx[jj];
                }
            }
        }
        if (tid < 64) ms[tid] = mask[b * SEQ + kt * 64 + tid];
        asm volatile("cp.async.wait_group 0;" ::: "memory");
        __syncthreads();

        float s[8][4] = {};
#pragma unroll
        for (int dk = 0; dk < 4; dk++) {
            uint32_t qh[4], ql[4];
            const int arow = w * 16 + ar_l;
            const uint32_t aoff = swz128(arow, 2 * dk + a_ch);
            ldsm4(qh, sb + AT_QH + aoff);
            ldsm4(ql, sb + AT_QL + aoff);
#pragma unroll
            for (int bj = 0; bj < 4; bj++) {
                uint32_t kb[4];
                const int krow = bj * 16 + br_l;
                ldsm4(kb, sb + AT_KH + swz128(krow, 2 * dk + b_ch));
                mma16816(s[2 * bj],     qh, kb);
                mma16816(s[2 * bj + 1], qh, kb + 2);
                mma16816(s[2 * bj],     ql, kb);
                mma16816(s[2 * bj + 1], ql, kb + 2);
            }
        }

        float rm0 = -1e30f, rm1 = -1e30f;
#pragma unroll
        for (int j = 0; j < 8; j++) {
            const int col = j * 8 + 2 * tig;
            const int k0 = ms[col], k1 = ms[col + 1];
            s[j][0] = k0 ? s[j][0] * 0.125f : -1e9f;
            s[j][1] = k1 ? s[j][1] * 0.125f : -1e9f;
            s[j][2] = k0 ? s[j][2] * 0.125f : -1e9f;
            s[j][3] = k1 ? s[j][3] * 0.125f : -1e9f;
            rm0 = fmaxf(rm0, fmaxf(s[j][0], s[j][1]));
            rm1 = fmaxf(rm1, fmaxf(s[j][2], s[j][3]));
        }
        rm0 = fmaxf(rm0, __shfl_xor_sync(0xffffffffu, rm0, 1));
        rm0 = fmaxf(rm0, __shfl_xor_sync(0xffffffffu, rm0, 2));
        rm1 = fmaxf(rm1, __shfl_xor_sync(0xffffffffu, rm1, 1));
        rm1 = fmaxf(rm1, __shfl_xor_sync(0xffffffffu, rm1, 2));

        const float mn0 = fmaxf(m0, rm0), mn1 = fmaxf(m1, rm1);
        const float sc0 = __expf(m0 - mn0), sc1 = __expf(m1 - mn1);
        m0 = mn0; m1 = mn1;

        float ps0 = 0.0f, ps1 = 0.0f;
#pragma unroll
        for (int j = 0; j < 8; j++) {
            s[j][0] = __expf(s[j][0] - mn0);
            s[j][1] = __expf(s[j][1] - mn0);
            s[j][2] = __expf(s[j][2] - mn1);
            s[j][3] = __expf(s[j][3] - mn1);
            ps0 += s[j][0] + s[j][1];
            ps1 += s[j][2] + s[j][3];
        }
        ps0 += __shfl_xor_sync(0xffffffffu, ps0, 1);
        ps0 += __shfl_xor_sync(0xffffffffu, ps0, 2);
        ps1 += __shfl_xor_sync(0xffffffffu, ps1, 1);
        ps1 += __shfl_xor_sync(0xffffffffu, ps1, 2);
        lsum0 = lsum0 * sc0 + ps0;
        lsum1 = lsum1 * sc1 + ps1;

#pragma unroll
        for (int dt = 0; dt < 8; dt++) {
            O[dt][0] *= sc0; O[dt][1] *= sc0;
            O[dt][2] *= sc1; O[dt][3] *= sc1;
        }

#pragma unroll
        for (int kk = 0; kk < 4; kk++) {
            uint32_t pah[4], pal[4];
            split2_h(s[2 * kk][0],     s[2 * kk][1],     pah[0], pal[0]);
            split2_h(s[2 * kk][2],     s[2 * kk][3],     pah[1], pal[1]);
            split2_h(s[2 * kk + 1][0], s[2 * kk + 1][1], pah[2], pal[2]);
            split2_h(s[2 * kk + 1][2], s[2 * kk + 1][3], pah[3], pal[3]);
#pragma unroll
            for (int dg = 0; dg < 4; dg++) {
                uint32_t bh[4], bl[4];
                const int drow = dg * 16 + br_l;
                const uint32_t bo = swz128(drow, 2 * kk + b_ch);
                ldsm4(bh, sb + AT_VTH + bo);
                ldsm4(bl, sb + AT_VTL + bo);
                mma16816(O[2 * dg],     pah, bh);
                mma16816(O[2 * dg + 1], pah, bh + 2);
                mma16816(O[2 * dg],     pah, bl);
                mma16816(O[2 * dg + 1], pah, bl + 2);
                mma16816(O[2 * dg],     pal, bh);
                mma16816(O[2 * dg + 1], pal, bh + 2);
            }
        }
    }

    const float inv0 = 1.0f / lsum0, inv1 = 1.0f / lsum1;
    const size_t row0 = brow + qt * 64 + w * 16 + gid;
    const size_t row1 = row0 + 8;
#pragma unroll
    for (int dt = 0; dt < 8; dt++) {
        const int col = h * 64 + dt * 8 + 2 * tig;
        uint32_t h0, l0u, h1, l1u;
        split2_h(O[dt][0] * inv0, O[dt][1] * inv0, h0, l0u);
        split2_h(O[dt][2] * inv1, O[dt][3] * inv1, h1, l1u);
        *(uint32_t*)(Oh + row0 * D_MODEL + col) = h0;
        *(uint32_t*)(Ol + row0 * D_MODEL + col) = l0u;
        *(uint32_t*)(Oh + row1 * D_MODEL + col) = h1;
        *(uint32_t*)(Ol + row1 * D_MODEL + col) = l1u;
    }
}

// ---------------- fused residual add + LayerNorm + optional fp16 split ------
__global__ __launch_bounds__(256)
void add_ln_kernel(const float* __restrict__ x,
                   const float* __restrict__ r,
                   const float* __restrict__ g,
                   const float* __restrict__ bta,
                   float* __restrict__ y,
                   __half* __restrict__ H,
                   __half* __restrict__ L,
                   int write_split) {
    const int row = blockIdx.x;
    const int tid = threadIdx.x;
    const int c = tid * 4;
    const size_t idx = (size_t)row * D_MODEL + c;

    float4 xv = *(const float4*)(x + idx);
    float4 rv = *(const float4*)(r + idx);
    float4 v;
    v.x = xv.x + rv.x; v.y = xv.y + rv.y;
    v.z = xv.z + rv.z; v.w = xv.w + rv.w;

    float s = v.x + v.y + v.z + v.w;
    float ss = fmaf(v.x, v.x, fmaf(v.y, v.y, fmaf(v.z, v.z, v.w * v.w)));

    __shared__ float rs[256], rss[256];
    rs[tid] = s; rss[tid] = ss;
    __syncthreads();
    for (int off = 128; off > 0; off >>= 1) {
        if (tid < off) { rs[tid] += rs[tid + off]; rss[tid] += rss[tid + off]; }
        __syncthreads();
    }
    float mean = rs[0] * (1.0f / D_MODEL);
    float var = rss[0] * (1.0f / D_MODEL) - mean * mean;
    float inv = rsqrtf(var + 1e-5f);

    float4 gg = *(const float4*)(g + c);
    float4 bb = *(const float4*)(bta + c);
    float4 o;
    o.x = (v.x - mean) * inv * gg.x + bb.x;
    o.y = (v.y - mean) * inv * gg.y + bb.y;
    o.z = (v.z - mean) * inv * gg.z + bb.z;
    o.w = (v.w - mean) * inv * gg.w + bb.w;
    *(float4*)(y + idx) = o;
    if (write_split) store_split4(H, L, idx, o);
}

// ---------------- host orchestration ---------------------------------------
extern "C" void kernel_launch(void* const* d_in, const int* in_sizes, int n_in,
                              void* d_out, int out_size) {
    const int*   src  = (const int*)d_in[0];
    const int*   mask = (const int*)d_in[1];
    const float* emb  = (const float*)d_in[2];
    const float* pe   = (const float*)d_in[3];
    const float* wq = (const float*)d_in[4];
    const float* bq = (const float*)d_in[5];
    const float* wk = (const float*)d_in[6];
    const float* bk = (const float*)d_in[7];
    const float* wv = (const float*)d_in[8];
    const float* bv = (const float*)d_in[9];
    const float* wo = (const float*)d_in[10];
    const float* bo = (const float*)d_in[11];
    const float* w1 = (const float*)d_in[12];
    const float* b1 = (const float*)d_in[13];
    const float* w2 = (const float*)d_in[14];
    const float* b2 = (const float*)d_in[15];
    const float* g1  = (const float*)d_in[16];
    const float* be1 = (const float*)d_in[17];
    const float* g2  = (const float*)d_in[18];
    const float* be2 = (const float*)d_in[19];
    float* out = (float*)d_out;

    float *px, *pt, *pbqkv;
    cudaGetSymbolAddress((void**)&px, g_x);
    cudaGetSymbolAddress((void**)&pt, g_t);
    cudaGetSymbolAddress((void**)&pbqkv, g_bqkv);

    __half *qkvh, *qkvl, *ah, *al, *hh;
    cudaGetSymbolAddress((void**)&qkvh, g_qkvh);
    cudaGetSymbolAddress((void**)&qkvl, g_qkvl);
    cudaGetSymbolAddress((void**)&ah, g_ah);
    cudaGetSymbolAddress((void**)&al, g_al);
    cudaGetSymbolAddress((void**)&hh, g_hh);

    __half *wqkvt, *wot, *w1t, *w2t;
    cudaGetSymbolAddress((void**)&wqkvt, g_wqkvt);
    cudaGetSymbolAddress((void**)&wot, g_wot);
    cudaGetSymbolAddress((void**)&w1t, g_w1t);
    cudaGetSymbolAddress((void**)&w2t, g_w2t);

    static int attr_set = 0;
    if (!attr_set) {
        cudaFuncSetAttribute(gemm_tc<1, 1, 0>,
                             cudaFuncAttributeMaxDynamicSharedMemorySize,
                             GEMM_SMEM_BYTES);
        cudaFuncSetAttribute(gemm_tc<1, 0, 0>,
                             cudaFuncAttributeMaxDynamicSharedMemorySize,
                             GEMM_SMEM_BYTES);
        cudaFuncSetAttribute(gemm_tc<0, 2, 1>,
                             cudaFuncAttributeMaxDynamicSharedMemorySize,
                             GEMM_SMEM_BYTES);
        cudaFuncSetAttribute(gemm_tc<0, 0, 0>,
                             cudaFuncAttributeMaxDynamicSharedMemorySize,
                             GEMM_SMEM_BYTES);
        cudaFuncSetAttribute(attn_mma_kernel,
                             cudaFuncAttributeMaxDynamicSharedMemorySize,
                             ATT_SMEM_BYTES);
        attr_set = 1;
    }

    // ---- weight prep: ONE launch ----
    prep_weights_kernel<<<dim3(12288, 1, 6), dim3(32, 8)>>>(
        wq, wk, wv, wo, w1, w2, wqkvt, wot, w1t, w2t);
    concat_bias_kernel<<<dim3(12, 6), 256>>>(bq, bk, bv, pbqkv);

    embed_kernel<<<ROWS, 256>>>(src, emb, pe, px, ah, al);

    dim3 g_qkv_grid(3072 / 128, ROWS / 128);   // (24, 32)
    dim3 g_dd(D_MODEL / 128, ROWS / 128);      // (8, 32)
    dim3 g_ff(D_FF / 128,    ROWS / 128);      // (32, 32)
    dim3 attn_grid(SEQ / 64, N_HEADS, BATCH);

    for (int l = 0; l < N_LAYERS; l++) {
        size_t woqkv = (size_t)l * 3072 * 1024;
        size_t wofs  = (size_t)l * 1024 * 1024;
        size_t bofs  = (size_t)l * D_MODEL;
        size_t wfofs = (size_t)l * 4096 * 1024;
        size_t b1ofs = (size_t)l * D_FF;

        // QKV projection (split-2 A, f32 acc) -> fp16 hi/lo
        gemm_tc<1, 1, 0><<<g_qkv_grid, 256, GEMM_SMEM_BYTES>>>(
            ah, al, wqkvt + woqkv, pbqkv + l * 3072,
            nullptr, qkvh, qkvl, ROWS, 3072, 1024);

        // tensor-core flash attention -> fp16 hi/lo (O-proj input)
        attn_mma_kernel<<<attn_grid, 128, ATT_SMEM_BYTES>>>(
            qkvh, qkvl, mask, ah, al);

        // O projection (split-2 A, f32 acc) -> fp32
        gemm_tc<1, 0, 0><<<g_dd, 256, GEMM_SMEM_BYTES>>>(
            ah, al, wot + wofs, bo + bofs,
            pt, nullptr, nullptr, ROWS, 1024, 1024);

        add_ln_kernel<<<ROWS, 256>>>(px, pt, g1 + bofs, be1 + bofs, px, ah, al, 1);

        // FFN1: single-term A, relu, fp16-hi out
        gemm_tc<0, 2, 1><<<g_ff, 256, GEMM_SMEM_BYTES>>>(
            ah, nullptr, w1t + wfofs, b1 + b1ofs,
            nullptr, hh, nullptr, ROWS, 4096, 1024);

        // FFN2: single-term A -> fp32
        gemm_tc<0, 0, 0><<<g_dd, 256, GEMM_SMEM_BYTES>>>(
            hh, nullptr, w2t + wfofs, b2 + bofs,
            pt, nullptr, nullptr, ROWS, 1024, 4096);

        if (l == N_LAYERS - 1) {
            add_ln_kernel<<<ROWS, 256>>>(px, pt, g2 + bofs, be2 + bofs, out,
                                         ah, al, 0);
        } else {
            add_ln_kernel<<<ROWS, 256>>>(px, pt, g2 + bofs, be2 + bofs, px,
                                         ah, al, 1);
        }
    }
}

// round 16
// speedup vs baseline: 1.2619x; 1.1141x over previous
#include <cuda_runtime.h>
#include <cuda_fp16.h>
#include <math.h>
#include <stdint.h>

#define D_MODEL 1024
#define N_HEADS 16
#define D_K 64
#define D_FF 4096
#define N_LAYERS 6
#define BATCH 4
#define SEQ 1024
#define ROWS (BATCH * SEQ)   // 4096

// ---------------- scratch (device globals; no allocation allowed) ----------
__device__ float g_x[ROWS * D_MODEL];                 // residual stream (fp32)
__device__ float g_t[ROWS * D_MODEL];                 // pre-LN gemm output
__device__ __half g_qkvh[(size_t)ROWS * 3 * D_MODEL]; // QKV fp16 hi
__device__ __half g_qkvl[(size_t)ROWS * 3 * D_MODEL]; // QKV fp16 lo (V-lo used)
__device__ __half g_ah[(size_t)ROWS * D_MODEL];       // activation hi
__device__ __half g_al[(size_t)ROWS * D_MODEL];       // activation lo
__device__ __half g_hh[(size_t)ROWS * D_FF];          // ffn hidden hi

// transposed weights: [N,K] K-major fp16
__device__ __half g_wqkvt[6u*3072*1024];
__device__ __half g_wot[6u*1024*1024];
__device__ __half g_w1t[6u*4096*1024];
__device__ __half g_w2t[6u*4096*1024];
__device__ float g_bqkv[6 * 3072];

// ---------------- PTX helpers ------------------------------------------------
__device__ __forceinline__ uint32_t smem_u32(const void* p) {
    uint32_t a;
    asm("{ .reg .u64 t; cvta.to.shared.u64 t, %1; cvt.u32.u64 %0, t; }"
        : "=r"(a) : "l"(p));
    return a;
}

__device__ __forceinline__ void cp16(uint32_t s, const void* g) {
    asm volatile("cp.async.cg.shared.global [%0], [%1], 16;"
                 :: "r"(s), "l"(g) : "memory");
}

__device__ __forceinline__ void ldsm4(uint32_t* r, uint32_t addr) {
    asm volatile("ldmatrix.sync.aligned.m8n8.x4.shared.b16 {%0,%1,%2,%3}, [%4];"
                 : "=r"(r[0]), "=r"(r[1]), "=r"(r[2]), "=r"(r[3]) : "r"(addr));
}

__device__ __forceinline__ void mma16816(float* c, const uint32_t* a,
                                         const uint32_t* b) {
    asm volatile(
        "mma.sync.aligned.m16n8k16.row.col.f32.f16.f16.f32 "
        "{%0,%1,%2,%3}, {%4,%5,%6,%7}, {%8,%9}, {%0,%1,%2,%3};"
        : "+f"(c[0]), "+f"(c[1]), "+f"(c[2]), "+f"(c[3])
        : "r"(a[0]), "r"(a[1]), "r"(a[2]), "r"(a[3]), "r"(b[0]), "r"(b[1]));
}

// split a float4 into fp16 hi/lo pairs, store 8B each
__device__ __forceinline__ void store_split4(__half* H, __half* L,
                                             size_t idx, float4 v) {
    __half2 h0 = __floats2half2_rn(v.x, v.y);
    __half2 h1 = __floats2half2_rn(v.z, v.w);
    float2 f0 = __half22float2(h0);
    float2 f1 = __half22float2(h1);
    __half2 l0 = __floats2half2_rn(v.x - f0.x, v.y - f0.y);
    __half2 l1 = __floats2half2_rn(v.z - f1.x, v.w - f1.y);
    uint2 hh, ll;
    hh.x = *reinterpret_cast<uint32_t*>(&h0);
    hh.y = *reinterpret_cast<uint32_t*>(&h1);
    ll.x = *reinterpret_cast<uint32_t*>(&l0);
    ll.y = *reinterpret_cast<uint32_t*>(&l1);
    *(uint2*)(H + idx) = hh;
    *(uint2*)(L + idx) = ll;
}

// split 2 floats into fp16 hi/lo half2 (as uint32)
__device__ __forceinline__ void split2_h(float a, float b,
                                         uint32_t& hi, uint32_t& lo) {
    __half2 h = __floats2half2_rn(a, b);
    float2 f = __half22float2(h);
    __half2 l = __floats2half2_rn(a - f.x, b - f.y);
    hi = *reinterpret_cast<uint32_t*>(&h);
    lo = *reinterpret_cast<uint32_t*>(&l);
}

// ---------------- single-launch weight prep (transpose + fp16 convert) ------
__global__ void prep_weights_kernel(
    const float* __restrict__ wq, const float* __restrict__ wk,
    const float* __restrict__ wv, const float* __restrict__ wo,
    const float* __restrict__ w1, const float* __restrict__ w2,
    __half* __restrict__ qkvt, __half* __restrict__ wot,
    __half* __restrict__ w1t,  __half* __restrict__ w2t) {
    __shared__ float t[32][33];
    const int tile = blockIdx.x;       // 0..12287
    const int layer = blockIdx.z;

    const float* W; __half* T;
    int K, N, row_off, tt; size_t lstride;
    if (tile < 1024)      { W = wq; T = qkvt; K = 1024; N = 1024;
                            row_off = 0;    lstride = (size_t)3072*1024; tt = tile; }
    else if (tile < 2048) { W = wk; T = qkvt; K = 1024; N = 1024;
                            row_off = 1024; lstride = (size_t)3072*1024; tt = tile - 1024; }
    else if (tile < 3072) { W = wv; T = qkvt; K = 1024; N = 1024;
                            row_off = 2048; lstride = (size_t)3072*1024; tt = tile - 2048; }
    else if (tile < 4096) { W = wo; T = wot;  K = 1024; N = 1024;
                            row_off = 0;    lstride = (size_t)1024*1024; tt = tile - 3072; }
    else if (tile < 8192) { W = w1; T = w1t;  K = 1024; N = 4096;
                            row_off = 0;    lstride = (size_t)4096*1024; tt = tile - 4096; }
    else                  { W = w2; T = w2t;  K = 4096; N = 1024;
                            row_off = 0;    lstride = (size_t)4096*1024; tt = tile - 8192; }

    const int ntiles = N >> 5;
    const int n0 = (tt % ntiles) * 32, k0 = (tt / ntiles) * 32;
    const float* Wl = W + (size_t)layer * K * N;
    const int tx = threadIdx.x, ty = threadIdx.y;
#pragma unroll
    for (int i = ty; i < 32; i += 8)
        t[i][tx] = Wl[(size_t)(k0 + i) * N + n0 + tx];
    __syncthreads();
#pragma unroll
    for (int i = ty; i < 32; i += 8) {
        size_t o = (size_t)layer * lstride +
                   (size_t)(row_off + n0 + i) * K + k0 + tx;
        T[o] = __float2half(t[tx][i]);
    }
}

__global__ void concat_bias_kernel(const float* __restrict__ bq,
                                   const float* __restrict__ bk,
                                   const float* __restrict__ bv,
                                   float* __restrict__ dst) {
    int l = blockIdx.y;
    int i = blockIdx.x * 256 + threadIdx.x;   // 0..3071
    float v;
    if (i < 1024) v = bq[l * 1024 + i];
    else if (i < 2048) v = bk[l * 1024 + i - 1024];
    else v = bv[l * 1024 + i - 2048];
    dst[l * 3072 + i] = v;
}

// ---------------- mma.sync fp16 GEMM, fp32 accumulate, templated ------------
// C[M,N] = (Ah [+ Al])[M,K] @ B[N,K]^T + bias.
// USE_ALO: split-2 A vs single-term. OUTMODE: 0=fp32 C, 1=fp16 hi/lo, 2=fp16 hi.
#define S_AH 0
#define S_AL 8192
#define S_B  16384
#define S_STG 24576
#define GEMM_SMEM_BYTES (3 * S_STG)   // 73728

template <int USE_ALO, int OUTMODE, int RELU>
__global__ __launch_bounds__(256, 2)
void gemm_tc(const __half* __restrict__ Ah,
             const __half* __restrict__ Al,
             const __half* __restrict__ B,
             const float* __restrict__ bias,
             float* __restrict__ C,
             __half* __restrict__ Hout,
             __half* __restrict__ Lout,
             int M, int N, int K) {
    extern __shared__ char sm[];
    const uint32_t sb = smem_u32(sm);

    const int tid = threadIdx.x;
    const int l = tid & 31, w = tid >> 5;
    const int wm = w & 3, wn = w >> 2;
    const int m0 = blockIdx.y * 128, n0 = blockIdx.x * 128;

    const int lr = tid >> 1;
    const int lkc = (tid & 1) * 2;
    const uint32_t off0 = lr * 64 + ((lkc ^ ((lr >> 1) & 3)) << 4);
    const uint32_t off1 = off0 ^ 16;

    const __half* agh = Ah + (size_t)(m0 + lr) * K + lkc * 8;
    const __half* agl = USE_ALO ? Al + (size_t)(m0 + lr) * K + lkc * 8 : nullptr;
    const __half* bg  = B  + (size_t)(n0 + lr) * K + lkc * 8;

    auto issue = [&](int c) {
        const uint32_t o = sb + (c % 3) * S_STG;
        const size_t go = (size_t)c * 32;
        cp16(o + S_AH + off0, agh + go);
        cp16(o + S_AH + off1, agh + go + 8);
        if (USE_ALO) {
            cp16(o + S_AL + off0, agl + go);
            cp16(o + S_AL + off1, agl + go + 8);
        }
        cp16(o + S_B  + off0, bg + go);
        cp16(o + S_B  + off1, bg + go + 8);
        asm volatile("cp.async.commit_group;" ::: "memory");
    };

    float acc[2][8][4] = {};

    const int NCk = K >> 5;
    issue(0);
    issue(1);

    const int ar_l = l & 15;
    const int a_ch = l >> 4;
    const int br_l = ((l >> 4) << 3) + (l & 7);
    const int b_ch = (l >> 3) & 1;

    for (int c = 0; c < NCk; c++) {
        if (c + 1 < NCk) {
            asm volatile("cp.async.wait_group 1;" ::: "memory");
        } else {
            asm volatile("cp.async.wait_group 0;" ::: "memory");
        }
        __syncthreads();
        if (c + 2 < NCk) issue(c + 2);

        const uint32_t o = sb + (c % 3) * S_STG;
#pragma unroll
        for (int ks = 0; ks < 2; ks++) {
            uint32_t ah[2][4], al_[2][4];
#pragma unroll
            for (int mi = 0; mi < 2; mi++) {
                const int ar = wm * 32 + mi * 16 + ar_l;
                const uint32_t aoff =
                    ar * 64 + (((2 * ks + a_ch) ^ ((ar >> 1) & 3)) << 4);
                ldsm4(ah[mi],  o + S_AH + aoff);
                if (USE_ALO) ldsm4(al_[mi], o + S_AL + aoff);
            }
#pragma unroll
            for (int njq = 0; njq < 8; njq += 4) {
                uint32_t b4[8];
                {
                    const int br0 = wn * 64 + njq * 8 + br_l;
                    const uint32_t bo0 =
                        br0 * 64 + (((2 * ks + b_ch) ^ ((br0 >> 1) & 3)) << 4);
                    ldsm4(b4,     o + S_B + bo0);
                    const int br1 = wn * 64 + (njq + 2) * 8 + br_l;
                    const uint32_t bo1 =
                        br1 * 64 + (((2 * ks + b_ch) ^ ((br1 >> 1) & 3)) << 4);
                    ldsm4(b4 + 4, o + S_B + bo1);
                }
#pragma unroll
                for (int mi = 0; mi < 2; mi++)
#pragma unroll
                    for (int j = 0; j < 4; j++)
                        mma16816(acc[mi][njq + j], ah[mi],
                                 &b4[(j >> 1) * 4 + (j & 1) * 2]);
                if (USE_ALO) {
#pragma unroll
                    for (int mi = 0; mi < 2; mi++)
#pragma unroll
                        for (int j = 0; j < 4; j++)
                            mma16816(acc[mi][njq + j], al_[mi],
                                     &b4[(j >> 1) * 4 + (j & 1) * 2]);
                }
            }
        }
    }

    const int gid = l >> 2, tig = l & 3;
#pragma unroll
    for (int mi = 0; mi < 2; mi++) {
        const int row0 = m0 + wm * 32 + mi * 16 + gid;
#pragma unroll
        for (int ni = 0; ni < 8; ni++) {
            const int col = n0 + wn * 64 + ni * 8 + tig * 2;
            float b0 = bias[col], b1 = bias[col + 1];
            float v0 = acc[mi][ni][0] + b0;
            float v1 = acc[mi][ni][1] + b1;
            float v2 = acc[mi][ni][2] + b0;
            float v3 = acc[mi][ni][3] + b1;
            if (RELU) {
                v0 = fmaxf(v0, 0.0f); v1 = fmaxf(v1, 0.0f);
                v2 = fmaxf(v2, 0.0f); v3 = fmaxf(v3, 0.0f);
            }
            if (OUTMODE == 0) {
                float2 p0 = {v0, v1}, p1 = {v2, v3};
                *(float2*)(C + (size_t)row0 * N + col) = p0;
                *(float2*)(C + (size_t)(row0 + 8) * N + col) = p1;
            } else if (OUTMODE == 1) {
                uint32_t h0, l0u, h1, l1u;
                split2_h(v0, v1, h0, l0u);
                split2_h(v2, v3, h1, l1u);
                *(uint32_t*)(Hout + (size_t)row0 * N + col) = h0;
                *(uint32_t*)(Lout + (size_t)row0 * N + col) = l0u;
                *(uint32_t*)(Hout + (size_t)(row0 + 8) * N + col) = h1;
                *(uint32_t*)(Lout + (size_t)(row0 + 8) * N + col) = l1u;
            } else {
                __half2 h0 = __floats2half2_rn(v0, v1);
                __half2 h1 = __floats2half2_rn(v2, v3);
                *(__half2*)(Hout + (size_t)row0 * N + col) = h0;
                *(__half2*)(Hout + (size_t)(row0 + 8) * N + col) = h1;
            }
        }
    }
}

// ---------------- embedding + PE, fused fp16 split ---------------------------
__global__ __launch_bounds__(256)
void embed_kernel(const int* __restrict__ src,
                  const float* __restrict__ emb,
                  const float* __restrict__ pe,
                  float* __restrict__ x,
                  __half* __restrict__ H,
                  __half* __restrict__ L) {
    int row = blockIdx.x;
    int s = row & (SEQ - 1);
    int tok = src[row];
    int c = threadIdx.x * 4;
    const float* erow = emb + (size_t)tok * D_MODEL;
    const float* prow = pe + (size_t)s * D_MODEL;
    float4 e = *(const float4*)(erow + c);
    float4 p = *(const float4*)(prow + c);
    float4 v;
    v.x = e.x * 32.0f + p.x; v.y = e.y * 32.0f + p.y;
    v.z = e.z * 32.0f + p.z; v.w = e.w * 32.0f + p.w;
    size_t idx = (size_t)row * D_MODEL + c;
    *(float4*)(x + idx) = v;
    store_split4(H, L, idx, v);
}

// ---------------- tensor-core flash attention --------------------------------
// S = Qh.Kh^T (1 term, measured-insensitive), AV = Ph.(Vh+Vl) (2 terms).
// Output: fp16 hi only (O-proj is single-term).
#define AT_QH 0
#define AT_KH 8192
#define AT_VTH 16384
#define AT_VTL 24576
#define AT_MS 32768
#define ATT_SMEM_BYTES (32768 + 256)
#define QKV_N 3072

__device__ __forceinline__ uint32_t swz128(int row, int ch) {
    return (uint32_t)(row * 128 + ((ch ^ (row & 7)) << 4));
}

__global__ __launch_bounds__(128)
void attn_mma_kernel(const __half* __restrict__ QKVh,
                     const __half* __restrict__ QKVl,
                     const int* __restrict__ mask,
                     __half* __restrict__ Oh) {
    extern __shared__ char sm[];
    const uint32_t sb = smem_u32(sm);
    int* ms = (int*)(sm + AT_MS);

    const int tid = threadIdx.x;
    const int l = tid & 31, w = tid >> 5;
    const int gid = l >> 2, tig = l & 3;
    const int qt = blockIdx.x, h = blockIdx.y, b = blockIdx.z;
    const size_t brow = (size_t)b * SEQ;

    // ---- load Qh (once)
    {
        const int row = tid >> 1;
        const size_t g = (brow + qt * 64 + row) * QKV_N + h * 64;
#pragma unroll
        for (int i = 0; i < 4; i++) {
            const int ch = (tid & 1) * 4 + i;
            cp16(sb + AT_QH + swz128(row, ch), QKVh + g + ch * 8);
        }
        asm volatile("cp.async.commit_group;" ::: "memory");
    }

    float m0 = -1e30f, m1 = -1e30f, lsum0 = 0.0f, lsum1 = 0.0f;
    float O[8][4] = {};

    const int ar_l = l & 15;
    const int a_ch = l >> 4;
    const int br_l = ((l >> 4) << 3) + (l & 7);
    const int b_ch = (l >> 3) & 1;

    for (int kt = 0; kt < SEQ / 64; kt++) {
        __syncthreads();
        // ---- Kh
        {
            const int row = tid >> 1;
            const size_t g = (brow + kt * 64 + row) * QKV_N + 1024 + h * 64;
#pragma unroll
            for (int i = 0; i < 4; i++) {
                const int ch = (tid & 1) * 4 + i;
                cp16(sb + AT_KH + swz128(row, ch), QKVh + g + ch * 8);
            }
            asm volatile("cp.async.commit_group;" ::: "memory");
        }
        // ---- V transposed (hi + lo)
        {
            const int kr = tid >> 1;
            const size_t g = (brow + kt * 64 + kr) * QKV_N + 2048 + h * 64;
#pragma unroll
            for (int i = 0; i < 4; i++) {
                const int dg = (tid & 1) * 4 + i;
                union { uint4 u; __half hx[8]; } vh, vl;
                vh.u = *(const uint4*)(QKVh + g + dg * 8);
                vl.u = *(const uint4*)(QKVl + g + dg * 8);
#pragma unroll
                for (int jj = 0; jj < 8; jj++) {
                    const int d = dg * 8 + jj;
                    const uint32_t o = (uint32_t)(d * 128 +
                        (((kr >> 3) ^ (d & 7)) << 4) + (kr & 7) * 2);
                    *(__half*)(sm + AT_VTH + o) = vh.hx[jj];
                    *(__half*)(sm + AT_VTL + o) = vl.hx[jj];
                }
            }
        }
        if (tid < 64) ms[tid] = mask[b * SEQ + kt * 64 + tid];
        asm volatile("cp.async.wait_group 0;" ::: "memory");
        __syncthreads();

        // ---- S = Qh . Kh^T
        float s[8][4] = {};
#pragma unroll
        for (int dk = 0; dk < 4; dk++) {
            uint32_t qh[4];
            const int arow = w * 16 + ar_l;
            ldsm4(qh, sb + AT_QH + swz128(arow, 2 * dk + a_ch));
#pragma unroll
            for (int bj = 0; bj < 4; bj++) {
                uint32_t kb[4];
                const int krow = bj * 16 + br_l;
                ldsm4(kb, sb + AT_KH + swz128(krow, 2 * dk + b_ch));
                mma16816(s[2 * bj],     qh, kb);
                mma16816(s[2 * bj + 1], qh, kb + 2);
            }
        }

        float rm0 = -1e30f, rm1 = -1e30f;
#pragma unroll
        for (int j = 0; j < 8; j++) {
            const int col = j * 8 + 2 * tig;
            const int k0 = ms[col], k1 = ms[col + 1];
            s[j][0] = k0 ? s[j][0] * 0.125f : -1e9f;
            s[j][1] = k1 ? s[j][1] * 0.125f : -1e9f;
            s[j][2] = k0 ? s[j][2] * 0.125f : -1e9f;
            s[j][3] = k1 ? s[j][3] * 0.125f : -1e9f;
            rm0 = fmaxf(rm0, fmaxf(s[j][0], s[j][1]));
            rm1 = fmaxf(rm1, fmaxf(s[j][2], s[j][3]));
        }
        rm0 = fmaxf(rm0, __shfl_xor_sync(0xffffffffu, rm0, 1));
        rm0 = fmaxf(rm0, __shfl_xor_sync(0xffffffffu, rm0, 2));
        rm1 = fmaxf(rm1, __shfl_xor_sync(0xffffffffu, rm1, 1));
        rm1 = fmaxf(rm1, __shfl_xor_sync(0xffffffffu, rm1, 2));

        const float mn0 = fmaxf(m0, rm0), mn1 = fmaxf(m1, rm1);
        const float sc0 = __expf(m0 - mn0), sc1 = __expf(m1 - mn1);
        m0 = mn0; m1 = mn1;

        float ps0 = 0.0f, ps1 = 0.0f;
#pragma unroll
        for (int j = 0; j < 8; j++) {
            s[j][0] = __expf(s[j][0] - mn0);
            s[j][1] = __expf(s[j][1] - mn0);
            s[j][2] = __expf(s[j][2] - mn1);
            s[j][3] = __expf(s[j][3] - mn1);
            ps0 += s[j][0] + s[j][1];
            ps1 += s[j][2] + s[j][3];
        }
        ps0 += __shfl_xor_sync(0xffffffffu, ps0, 1);
        ps0 += __shfl_xor_sync(0xffffffffu, ps0, 2);
        ps1 += __shfl_xor_sync(0xffffffffu, ps1, 1);
        ps1 += __shfl_xor_sync(0xffffffffu, ps1, 2);
        lsum0 = lsum0 * sc0 + ps0;
        lsum1 = lsum1 * sc1 + ps1;

#pragma unroll
        for (int dt = 0; dt < 8; dt++) {
            O[dt][0] *= sc0; O[dt][1] *= sc0;
            O[dt][2] *= sc1; O[dt][3] *= sc1;
        }

        // ---- O += Ph . (Vh + Vl)
#pragma unroll
        for (int kk = 0; kk < 4; kk++) {
            uint32_t pah[4];
            {
                __half2 p0 = __floats2half2_rn(s[2 * kk][0], s[2 * kk][1]);
                __half2 p1 = __floats2half2_rn(s[2 * kk][2], s[2 * kk][3]);
                __half2 p2 = __floats2half2_rn(s[2 * kk + 1][0], s[2 * kk + 1][1]);
                __half2 p3 = __floats2half2_rn(s[2 * kk + 1][2], s[2 * kk + 1][3]);
                pah[0] = *reinterpret_cast<uint32_t*>(&p0);
                pah[1] = *reinterpret_cast<uint32_t*>(&p1);
                pah[2] = *reinterpret_cast<uint32_t*>(&p2);
                pah[3] = *reinterpret_cast<uint32_t*>(&p3);
            }
#pragma unroll
            for (int dg = 0; dg < 4; dg++) {
                uint32_t bh[4], bl[4];
                const int drow = dg * 16 + br_l;
                const uint32_t bo = swz128(drow, 2 * kk + b_ch);
                ldsm4(bh, sb + AT_VTH + bo);
                ldsm4(bl, sb + AT_VTL + bo);
                mma16816(O[2 * dg],     pah, bh);
                mma16816(O[2 * dg + 1], pah, bh + 2);
                mma16816(O[2 * dg],     pah, bl);
                mma16816(O[2 * dg + 1], pah, bl + 2);
            }
        }
    }

    // ---- epilogue: normalize + fp16 write (single-term O-proj input)
    const float inv0 = 1.0f / lsum0, inv1 = 1.0f / lsum1;
    const size_t row0 = brow + qt * 64 + w * 16 + gid;
    const size_t row1 = row0 + 8;
#pragma unroll
    for (int dt = 0; dt < 8; dt++) {
        const int col = h * 64 + dt * 8 + 2 * tig;
        __half2 h0 = __floats2half2_rn(O[dt][0] * inv0, O[dt][1] * inv0);
        __half2 h1 = __floats2half2_rn(O[dt][2] * inv1, O[dt][3] * inv1);
        *(__half2*)(Oh + row0 * D_MODEL + col) = h0;
        *(__half2*)(Oh + row1 * D_MODEL + col) = h1;
    }
}

// ---------------- fused residual add + LayerNorm + optional fp16 split ------
__global__ __launch_bounds__(256)
void add_ln_kernel(const float* __restrict__ x,
                   const float* __restrict__ r,
                   const float* __restrict__ g,
                   const float* __restrict__ bta,
                   float* __restrict__ y,
                   __half* __restrict__ H,
                   __half* __restrict__ L,
                   int write_split) {
    const int row = blockIdx.x;
    const int tid = threadIdx.x;
    const int c = tid * 4;
    const size_t idx = (size_t)row * D_MODEL + c;

    float4 xv = *(const float4*)(x + idx);
    float4 rv = *(const float4*)(r + idx);
    float4 v;
    v.x = xv.x + rv.x; v.y = xv.y + rv.y;
    v.z = xv.z + rv.z; v.w = xv.w + rv.w;

    float s = v.x + v.y + v.z + v.w;
    float ss = fmaf(v.x, v.x, fmaf(v.y, v.y, fmaf(v.z, v.z, v.w * v.w)));

    __shared__ float rs[256], rss[256];
    rs[tid] = s; rss[tid] = ss;
    __syncthreads();
    for (int off = 128; off > 0; off >>= 1) {
        if (tid < off) { rs[tid] += rs[tid + off]; rss[tid] += rss[tid + off]; }
        __syncthreads();
    }
    float mean = rs[0] * (1.0f / D_MODEL);
    float var = rss[0] * (1.0f / D_MODEL) - mean * mean;
    float inv = rsqrtf(var + 1e-5f);

    float4 gg = *(const float4*)(g + c);
    float4 bb = *(const float4*)(bta + c);
    float4 o;
    o.x = (v.x - mean) * inv * gg.x + bb.x;
    o.y = (v.y - mean) * inv * gg.y + bb.y;
    o.z = (v.z - mean) * inv * gg.z + bb.z;
    o.w = (v.w - mean) * inv * gg.w + bb.w;
    *(float4*)(y + idx) = o;
    if (write_split) store_split4(H, L, idx, o);
}

// ---------------- host orchestration ---------------------------------------
extern "C" void kernel_launch(void* const* d_in, const int* in_sizes, int n_in,
                              void* d_out, int out_size) {
    const int*   src  = (const int*)d_in[0];
    const int*   mask = (const int*)d_in[1];
    const float* emb  = (const float*)d_in[2];
    const float* pe   = (const float*)d_in[3];
    const float* wq = (const float*)d_in[4];
    const float* bq = (const float*)d_in[5];
    const float* wk = (const float*)d_in[6];
    const float* bk = (const float*)d_in[7];
    const float* wv = (const float*)d_in[8];
    const float* bv = (const float*)d_in[9];
    const float* wo = (const float*)d_in[10];
    const float* bo = (const float*)d_in[11];
    const float* w1 = (const float*)d_in[12];
    const float* b1 = (const float*)d_in[13];
    const float* w2 = (const float*)d_in[14];
    const float* b2 = (const float*)d_in[15];
    const float* g1  = (const float*)d_in[16];
    const float* be1 = (const float*)d_in[17];
    const float* g2  = (const float*)d_in[18];
    const float* be2 = (const float*)d_in[19];
    float* out = (float*)d_out;

    float *px, *pt, *pbqkv;
    cudaGetSymbolAddress((void**)&px, g_x);
    cudaGetSymbolAddress((void**)&pt, g_t);
    cudaGetSymbolAddress((void**)&pbqkv, g_bqkv);

    __half *qkvh, *qkvl, *ah, *al, *hh;
    cudaGetSymbolAddress((void**)&qkvh, g_qkvh);
    cudaGetSymbolAddress((void**)&qkvl, g_qkvl);
    cudaGetSymbolAddress((void**)&ah, g_ah);
    cudaGetSymbolAddress((void**)&al, g_al);
    cudaGetSymbolAddress((void**)&hh, g_hh);

    __half *wqkvt, *wot, *w1t, *w2t;
    cudaGetSymbolAddress((void**)&wqkvt, g_wqkvt);
    cudaGetSymbolAddress((void**)&wot, g_wot);
    cudaGetSymbolAddress((void**)&w1t, g_w1t);
    cudaGetSymbolAddress((void**)&w2t, g_w2t);

    static int attr_set = 0;
    if (!attr_set) {
        cudaFuncSetAttribute(gemm_tc<1, 1, 0>,
                             cudaFuncAttributeMaxDynamicSharedMemorySize,
                             GEMM_SMEM_BYTES);
        cudaFuncSetAttribute(gemm_tc<0, 2, 1>,
                             cudaFuncAttributeMaxDynamicSharedMemorySize,
                             GEMM_SMEM_BYTES);
        cudaFuncSetAttribute(gemm_tc<0, 0, 0>,
                             cudaFuncAttributeMaxDynamicSharedMemorySize,
                             GEMM_SMEM_BYTES);
        cudaFuncSetAttribute(attn_mma_kernel,
                             cudaFuncAttributeMaxDynamicSharedMemorySize,
                             ATT_SMEM_BYTES);
        attr_set = 1;
    }

    // ---- weight prep: ONE launch ----
    prep_weights_kernel<<<dim3(12288, 1, 6), dim3(32, 8)>>>(
        wq, wk, wv, wo, w1, w2, wqkvt, wot, w1t, w2t);
    concat_bias_kernel<<<dim3(12, 6), 256>>>(bq, bk, bv, pbqkv);

    embed_kernel<<<ROWS, 256>>>(src, emb, pe, px, ah, al);

    dim3 g_qkv_grid(3072 / 128, ROWS / 128);   // (24, 32)
    dim3 g_dd(D_MODEL / 128, ROWS / 128);      // (8, 32)
    dim3 g_ff(D_FF / 128,    ROWS / 128);      // (32, 32)
    dim3 attn_grid(SEQ / 64, N_HEADS, BATCH);

    for (int l = 0; l < N_LAYERS; l++) {
        size_t woqkv = (size_t)l * 3072 * 1024;
        size_t wofs  = (size_t)l * 1024 * 1024;
        size_t bofs  = (size_t)l * D_MODEL;
        size_t wfofs = (size_t)l * 4096 * 1024;
        size_t b1ofs = (size_t)l * D_FF;

        // QKV projection (split-2 A, f32 acc) -> fp16 hi/lo
        gemm_tc<1, 1, 0><<<g_qkv_grid, 256, GEMM_SMEM_BYTES>>>(
            ah, al, wqkvt + woqkv, pbqkv + l * 3072,
            nullptr, qkvh, qkvl, ROWS, 3072, 1024);

        // flash attention (S: Qh.Kh, AV: Ph.(Vh+Vl)) -> fp16 hi
        attn_mma_kernel<<<attn_grid, 128, ATT_SMEM_BYTES>>>(
            qkvh, qkvl, mask, ah);

        // O projection (single-term A) -> fp32
        gemm_tc<0, 0, 0><<<g_dd, 256, GEMM_SMEM_BYTES>>>(
            ah, nullptr, wot + wofs, bo + bofs,
            pt, nullptr, nullptr, ROWS, 1024, 1024);

        add_ln_kernel<<<ROWS, 256>>>(px, pt, g1 + bofs, be1 + bofs, px, ah, al, 1);

        // FFN1: single-term A, relu, fp16-hi out
        gemm_tc<0, 2, 1><<<g_ff, 256, GEMM_SMEM_BYTES>>>(
            ah, nullptr, w1t + wfofs, b1 + b1ofs,
            nullptr, hh, nullptr, ROWS, 4096, 1024);

        // FFN2: single-term A -> fp32
        gemm_tc<0, 0, 0><<<g_dd, 256, GEMM_SMEM_BYTES>>>(
            hh, nullptr, w2t + wfofs, b2 + bofs,
            pt, nullptr, nullptr, ROWS, 1024, 4096);

        if (l == N_LAYERS - 1) {
            add_ln_kernel<<<ROWS, 256>>>(px, pt, g2 + bofs, be2 + bofs, out,
                                         ah, al, 0);
        } else {
            add_ln_kernel<<<ROWS, 256>>>(px, pt, g2 + bofs, be2 + bofs, px,
                                         ah, al, 1);
        }
    }
}

// round 17
// speedup vs baseline: 1.3847x; 1.0973x over previous
#include <cuda_runtime.h>
#include <cuda_fp16.h>
#include <math.h>
#include <stdint.h>

#define D_MODEL 1024
#define N_HEADS 16
#define D_K 64
#define D_FF 4096
#define N_LAYERS 6
#define BATCH 4
#define SEQ 1024
#define ROWS (BATCH * SEQ)   // 4096

// ---------------- scratch (device globals; no allocation allowed) ----------
__device__ float g_x[ROWS * D_MODEL];                 // residual stream (fp32)
__device__ float g_t[ROWS * D_MODEL];                 // pre-LN gemm output
__device__ __half g_qkvh[(size_t)ROWS * 3 * D_MODEL]; // QKV fp16 hi
__device__ __half g_qkvl[(size_t)ROWS * 3 * D_MODEL]; // QKV fp16 lo (V-lo used)
__device__ __half g_ah[(size_t)ROWS * D_MODEL];       // activation (fp16)
__device__ __half g_hh[(size_t)ROWS * D_FF];          // ffn hidden (fp16)

// transposed weights: [N,K] K-major fp16
__device__ __half g_wqkvt[6u*3072*1024];
__device__ __half g_wot[6u*1024*1024];
__device__ __half g_w1t[6u*4096*1024];
__device__ __half g_w2t[6u*4096*1024];
__device__ float g_bqkv[6 * 3072];

// ---------------- PTX helpers ------------------------------------------------
__device__ __forceinline__ uint32_t smem_u32(const void* p) {
    uint32_t a;
    asm("{ .reg .u64 t; cvta.to.shared.u64 t, %1; cvt.u32.u64 %0, t; }"
        : "=r"(a) : "l"(p));
    return a;
}

__device__ __forceinline__ void cp16(uint32_t s, const void* g) {
    asm volatile("cp.async.cg.shared.global [%0], [%1], 16;"
                 :: "r"(s), "l"(g) : "memory");
}

__device__ __forceinline__ void ldsm4(uint32_t* r, uint32_t addr) {
    asm volatile("ldmatrix.sync.aligned.m8n8.x4.shared.b16 {%0,%1,%2,%3}, [%4];"
                 : "=r"(r[0]), "=r"(r[1]), "=r"(r[2]), "=r"(r[3]) : "r"(addr));
}

__device__ __forceinline__ void mma16816(float* c, const uint32_t* a,
                                         const uint32_t* b) {
    asm volatile(
        "mma.sync.aligned.m16n8k16.row.col.f32.f16.f16.f32 "
        "{%0,%1,%2,%3}, {%4,%5,%6,%7}, {%8,%9}, {%0,%1,%2,%3};"
        : "+f"(c[0]), "+f"(c[1]), "+f"(c[2]), "+f"(c[3])
        : "r"(a[0]), "r"(a[1]), "r"(a[2]), "r"(a[3]), "r"(b[0]), "r"(b[1]));
}

// store a float4 as 4 fp16 (8B)
__device__ __forceinline__ void store_h4(__half* H, size_t idx, float4 v) {
    __half2 h0 = __floats2half2_rn(v.x, v.y);
    __half2 h1 = __floats2half2_rn(v.z, v.w);
    uint2 hh;
    hh.x = *reinterpret_cast<uint32_t*>(&h0);
    hh.y = *reinterpret_cast<uint32_t*>(&h1);
    *(uint2*)(H + idx) = hh;
}

// split 2 floats into fp16 hi/lo half2 (as uint32)
__device__ __forceinline__ void split2_h(float a, float b,
                                         uint32_t& hi, uint32_t& lo) {
    __half2 h = __floats2half2_rn(a, b);
    float2 f = __half22float2(h);
    __half2 l = __floats2half2_rn(a - f.x, b - f.y);
    hi = *reinterpret_cast<uint32_t*>(&h);
    lo = *reinterpret_cast<uint32_t*>(&l);
}

// ---------------- single-launch weight prep (transpose + fp16 convert) ------
__global__ void prep_weights_kernel(
    const float* __restrict__ wq, const float* __restrict__ wk,
    const float* __restrict__ wv, const float* __restrict__ wo,
    const float* __restrict__ w1, const float* __restrict__ w2,
    __half* __restrict__ qkvt, __half* __restrict__ wot,
    __half* __restrict__ w1t,  __half* __restrict__ w2t) {
    __shared__ float t[32][33];
    const int tile = blockIdx.x;       // 0..12287
    const int layer = blockIdx.z;

    const float* W; __half* T;
    int K, N, row_off, tt; size_t lstride;
    if (tile < 1024)      { W = wq; T = qkvt; K = 1024; N = 1024;
                            row_off = 0;    lstride = (size_t)3072*1024; tt = tile; }
    else if (tile < 2048) { W = wk; T = qkvt; K = 1024; N = 1024;
                            row_off = 1024; lstride = (size_t)3072*1024; tt = tile - 1024; }
    else if (tile < 3072) { W = wv; T = qkvt; K = 1024; N = 1024;
                            row_off = 2048; lstride = (size_t)3072*1024; tt = tile - 2048; }
    else if (tile < 4096) { W = wo; T = wot;  K = 1024; N = 1024;
                            row_off = 0;    lstride = (size_t)1024*1024; tt = tile - 3072; }
    else if (tile < 8192) { W = w1; T = w1t;  K = 1024; N = 4096;
                            row_off = 0;    lstride = (size_t)4096*1024; tt = tile - 4096; }
    else                  { W = w2; T = w2t;  K = 4096; N = 1024;
                            row_off = 0;    lstride = (size_t)4096*1024; tt = tile - 8192; }

    const int ntiles = N >> 5;
    const int n0 = (tt % ntiles) * 32, k0 = (tt / ntiles) * 32;
    const float* Wl = W + (size_t)layer * K * N;
    const int tx = threadIdx.x, ty = threadIdx.y;
#pragma unroll
    for (int i = ty; i < 32; i += 8)
        t[i][tx] = Wl[(size_t)(k0 + i) * N + n0 + tx];
    __syncthreads();
#pragma unroll
    for (int i = ty; i < 32; i += 8) {
        size_t o = (size_t)layer * lstride +
                   (size_t)(row_off + n0 + i) * K + k0 + tx;
        T[o] = __float2half(t[tx][i]);
    }
}

__global__ void concat_bias_kernel(const float* __restrict__ bq,
                                   const float* __restrict__ bk,
                                   const float* __restrict__ bv,
                                   float* __restrict__ dst) {
    int l = blockIdx.y;
    int i = blockIdx.x * 256 + threadIdx.x;   // 0..3071
    float v;
    if (i < 1024) v = bq[l * 1024 + i];
    else if (i < 2048) v = bk[l * 1024 + i - 1024];
    else v = bv[l * 1024 + i - 2048];
    dst[l * 3072 + i] = v;
}

// ---------------- mma.sync fp16 GEMM, fp32 accumulate, templated ------------
// C[M,N] = A[M,K] @ B[N,K]^T + bias (single-term A).
// OUTMODE: 0=fp32 C, 1=fp16 hi/lo, 2=fp16 hi.
#define S_AH 0
#define S_B  8192
#define S_STG 16384
#define GEMM_SMEM_BYTES (3 * S_STG)   // 49152

template <int OUTMODE, int RELU>
__global__ __launch_bounds__(256, 2)
void gemm_tc(const __half* __restrict__ Ah,
             const __half* __restrict__ B,
             const float* __restrict__ bias,
             float* __restrict__ C,
             __half* __restrict__ Hout,
             __half* __restrict__ Lout,
             int M, int N, int K) {
    extern __shared__ char sm[];
    const uint32_t sb = smem_u32(sm);

    const int tid = threadIdx.x;
    const int l = tid & 31, w = tid >> 5;
    const int wm = w & 3, wn = w >> 2;
    const int m0 = blockIdx.y * 128, n0 = blockIdx.x * 128;

    const int lr = tid >> 1;
    const int lkc = (tid & 1) * 2;
    const uint32_t off0 = lr * 64 + ((lkc ^ ((lr >> 1) & 3)) << 4);
    const uint32_t off1 = off0 ^ 16;

    const __half* agh = Ah + (size_t)(m0 + lr) * K + lkc * 8;
    const __half* bg  = B  + (size_t)(n0 + lr) * K + lkc * 8;

    auto issue = [&](int c) {
        const uint32_t o = sb + (c % 3) * S_STG;
        const size_t go = (size_t)c * 32;
        cp16(o + S_AH + off0, agh + go);
        cp16(o + S_AH + off1, agh + go + 8);
        cp16(o + S_B  + off0, bg + go);
        cp16(o + S_B  + off1, bg + go + 8);
        asm volatile("cp.async.commit_group;" ::: "memory");
    };

    float acc[2][8][4] = {};

    const int NCk = K >> 5;
    issue(0);
    issue(1);

    const int ar_l = l & 15;
    const int a_ch = l >> 4;
    const int br_l = ((l >> 4) << 3) + (l & 7);
    const int b_ch = (l >> 3) & 1;

    for (int c = 0; c < NCk; c++) {
        if (c + 1 < NCk) {
            asm volatile("cp.async.wait_group 1;" ::: "memory");
        } else {
            asm volatile("cp.async.wait_group 0;" ::: "memory");
        }
        __syncthreads();
        if (c + 2 < NCk) issue(c + 2);

        const uint32_t o = sb + (c % 3) * S_STG;
#pragma unroll
        for (int ks = 0; ks < 2; ks++) {
            uint32_t ah[2][4];
#pragma unroll
            for (int mi = 0; mi < 2; mi++) {
                const int ar = wm * 32 + mi * 16 + ar_l;
                const uint32_t aoff =
                    ar * 64 + (((2 * ks + a_ch) ^ ((ar >> 1) & 3)) << 4);
                ldsm4(ah[mi], o + S_AH + aoff);
            }
#pragma unroll
            for (int njq = 0; njq < 8; njq += 4) {
                uint32_t b4[8];
                {
                    const int br0 = wn * 64 + njq * 8 + br_l;
                    const uint32_t bo0 =
                        br0 * 64 + (((2 * ks + b_ch) ^ ((br0 >> 1) & 3)) << 4);
                    ldsm4(b4,     o + S_B + bo0);
                    const int br1 = wn * 64 + (njq + 2) * 8 + br_l;
                    const uint32_t bo1 =
                        br1 * 64 + (((2 * ks + b_ch) ^ ((br1 >> 1) & 3)) << 4);
                    ldsm4(b4 + 4, o + S_B + bo1);
                }
#pragma unroll
                for (int mi = 0; mi < 2; mi++)
#pragma unroll
                    for (int j = 0; j < 4; j++)
                        mma16816(acc[mi][njq + j], ah[mi],
                                 &b4[(j >> 1) * 4 + (j & 1) * 2]);
            }
        }
    }

    const int gid = l >> 2, tig = l & 3;
#pragma unroll
    for (int mi = 0; mi < 2; mi++) {
        const int row0 = m0 + wm * 32 + mi * 16 + gid;
#pragma unroll
        for (int ni = 0; ni < 8; ni++) {
            const int col = n0 + wn * 64 + ni * 8 + tig * 2;
            float b0 = bias[col], b1 = bias[col + 1];
            float v0 = acc[mi][ni][0] + b0;
            float v1 = acc[mi][ni][1] + b1;
            float v2 = acc[mi][ni][2] + b0;
            float v3 = acc[mi][ni][3] + b1;
            if (RELU) {
                v0 = fmaxf(v0, 0.0f); v1 = fmaxf(v1, 0.0f);
                v2 = fmaxf(v2, 0.0f); v3 = fmaxf(v3, 0.0f);
            }
            if (OUTMODE == 0) {
                float2 p0 = {v0, v1}, p1 = {v2, v3};
                *(float2*)(C + (size_t)row0 * N + col) = p0;
                *(float2*)(C + (size_t)(row0 + 8) * N + col) = p1;
            } else if (OUTMODE == 1) {
                uint32_t h0, l0u, h1, l1u;
                split2_h(v0, v1, h0, l0u);
                split2_h(v2, v3, h1, l1u);
                *(uint32_t*)(Hout + (size_t)row0 * N + col) = h0;
                *(uint32_t*)(Lout + (size_t)row0 * N + col) = l0u;
                *(uint32_t*)(Hout + (size_t)(row0 + 8) * N + col) = h1;
                *(uint32_t*)(Lout + (size_t)(row0 + 8) * N + col) = l1u;
            } else {
                __half2 h0 = __floats2half2_rn(v0, v1);
                __half2 h1 = __floats2half2_rn(v2, v3);
                *(__half2*)(Hout + (size_t)row0 * N + col) = h0;
                *(__half2*)(Hout + (size_t)(row0 + 8) * N + col) = h1;
            }
        }
    }
}

// ---------------- embedding + PE, fp16 convert -------------------------------
__global__ __launch_bounds__(256)
void embed_kernel(const int* __restrict__ src,
                  const float* __restrict__ emb,
                  const float* __restrict__ pe,
                  float* __restrict__ x,
                  __half* __restrict__ H) {
    int row = blockIdx.x;
    int s = row & (SEQ - 1);
    int tok = src[row];
    int c = threadIdx.x * 4;
    const float* erow = emb + (size_t)tok * D_MODEL;
    const float* prow = pe + (size_t)s * D_MODEL;
    float4 e = *(const float4*)(erow + c);
    float4 p = *(const float4*)(prow + c);
    float4 v;
    v.x = e.x * 32.0f + p.x; v.y = e.y * 32.0f + p.y;
    v.z = e.z * 32.0f + p.z; v.w = e.w * 32.0f + p.w;
    size_t idx = (size_t)row * D_MODEL + c;
    *(float4*)(x + idx) = v;
    store_h4(H, idx, v);
}

// ---------------- tensor-core flash attention --------------------------------
// S = Qh.Kh^T (1 term), AV = Ph.(Vh+Vl) (2 terms). Output: fp16 hi.
#define AT_QH 0
#define AT_KH 8192
#define AT_VTH 16384
#define AT_VTL 24576
#define AT_MS 32768
#define ATT_SMEM_BYTES (32768 + 256)
#define QKV_N 3072

__device__ __forceinline__ uint32_t swz128(int row, int ch) {
    return (uint32_t)(row * 128 + ((ch ^ (row & 7)) << 4));
}

__global__ __launch_bounds__(128)
void attn_mma_kernel(const __half* __restrict__ QKVh,
                     const __half* __restrict__ QKVl,
                     const int* __restrict__ mask,
                     __half* __restrict__ Oh) {
    extern __shared__ char sm[];
    const uint32_t sb = smem_u32(sm);
    int* ms = (int*)(sm + AT_MS);

    const int tid = threadIdx.x;
    const int l = tid & 31, w = tid >> 5;
    const int gid = l >> 2, tig = l & 3;
    const int qt = blockIdx.x, h = blockIdx.y, b = blockIdx.z;
    const size_t brow = (size_t)b * SEQ;

    {
        const int row = tid >> 1;
        const size_t g = (brow + qt * 64 + row) * QKV_N + h * 64;
#pragma unroll
        for (int i = 0; i < 4; i++) {
            const int ch = (tid & 1) * 4 + i;
            cp16(sb + AT_QH + swz128(row, ch), QKVh + g + ch * 8);
        }
        asm volatile("cp.async.commit_group;" ::: "memory");
    }

    float m0 = -1e30f, m1 = -1e30f, lsum0 = 0.0f, lsum1 = 0.0f;
    float O[8][4] = {};

    const int ar_l = l & 15;
    const int a_ch = l >> 4;
    const int br_l = ((l >> 4) << 3) + (l & 7);
    const int b_ch = (l >> 3) & 1;

    for (int kt = 0; kt < SEQ / 64; kt++) {
        __syncthreads();
        {
            const int row = tid >> 1;
            const size_t g = (brow + kt * 64 + row) * QKV_N + 1024 + h * 64;
#pragma unroll
            for (int i = 0; i < 4; i++) {
                const int ch = (tid & 1) * 4 + i;
                cp16(sb + AT_KH + swz128(row, ch), QKVh + g + ch * 8);
            }
            asm volatile("cp.async.commit_group;" ::: "memory");
        }
        {
            const int kr = tid >> 1;
            const size_t g = (brow + kt * 64 + kr) * QKV_N + 2048 + h * 64;
#pragma unroll
            for (int i = 0; i < 4; i++) {
                const int dg = (tid & 1) * 4 + i;
                union { uint4 u; __half hx[8]; } vh, vl;
                vh.u = *(const uint4*)(QKVh + g + dg * 8);
                vl.u = *(const uint4*)(QKVl + g + dg * 8);
#pragma unroll
                for (int jj = 0; jj < 8; jj++) {
                    const int d = dg * 8 + jj;
                    const uint32_t o = (uint32_t)(d * 128 +
                        (((kr >> 3) ^ (d & 7)) << 4) + (kr & 7) * 2);
                    *(__half*)(sm + AT_VTH + o) = vh.hx[jj];
                    *(__half*)(sm + AT_VTL + o) = vl.hx[jj];
                }
            }
        }
        if (tid < 64) ms[tid] = mask[b * SEQ + kt * 64 + tid];
        asm volatile("cp.async.wait_group 0;" ::: "memory");
        __syncthreads();

        float s[8][4] = {};
#pragma unroll
        for (int dk = 0; dk < 4; dk++) {
            uint32_t qh[4];
            const int arow = w * 16 + ar_l;
            ldsm4(qh, sb + AT_QH + swz128(arow, 2 * dk + a_ch));
#pragma unroll
            for (int bj = 0; bj < 4; bj++) {
                uint32_t kb[4];
                const int krow = bj * 16 + br_l;
                ldsm4(kb, sb + AT_KH + swz128(krow, 2 * dk + b_ch));
                mma16816(s[2 * bj],     qh, kb);
                mma16816(s[2 * bj + 1], qh, kb + 2);
            }
        }

        float rm0 = -1e30f, rm1 = -1e30f;
#pragma unroll
        for (int j = 0; j < 8; j++) {
            const int col = j * 8 + 2 * tig;
            const int k0 = ms[col], k1 = ms[col + 1];
            s[j][0] = k0 ? s[j][0] * 0.125f : -1e9f;
            s[j][1] = k1 ? s[j][1] * 0.125f : -1e9f;
            s[j][2] = k0 ? s[j][2] * 0.125f : -1e9f;
            s[j][3] = k1 ? s[j][3] * 0.125f : -1e9f;
            rm0 = fmaxf(rm0, fmaxf(s[j][0], s[j][1]));
            rm1 = fmaxf(rm1, fmaxf(s[j][2], s[j][3]));
        }
        rm0 = fmaxf(rm0, __shfl_xor_sync(0xffffffffu, rm0, 1));
        rm0 = fmaxf(rm0, __shfl_xor_sync(0xffffffffu, rm0, 2));
        rm1 = fmaxf(rm1, __shfl_xor_sync(0xffffffffu, rm1, 1));
        rm1 = fmaxf(rm1, __shfl_xor_sync(0xffffffffu, rm1, 2));

        const float mn0 = fmaxf(m0, rm0), mn1 = fmaxf(m1, rm1);
        const float sc0 = __expf(m0 - mn0), sc1 = __expf(m1 - mn1);
        m0 = mn0; m1 = mn1;

        float ps0 = 0.0f, ps1 = 0.0f;
#pragma unroll
        for (int j = 0; j < 8; j++) {
            s[j][0] = __expf(s[j][0] - mn0);
            s[j][1] = __expf(s[j][1] - mn0);
            s[j][2] = __expf(s[j][2] - mn1);
            s[j][3] = __expf(s[j][3] - mn1);
            ps0 += s[j][0] + s[j][1];
            ps1 += s[j][2] + s[j][3];
        }
        ps0 += __shfl_xor_sync(0xffffffffu, ps0, 1);
        ps0 += __shfl_xor_sync(0xffffffffu, ps0, 2);
        ps1 += __shfl_xor_sync(0xffffffffu, ps1, 1);
        ps1 += __shfl_xor_sync(0xffffffffu, ps1, 2);
        lsum0 = lsum0 * sc0 + ps0;
        lsum1 = lsum1 * sc1 + ps1;

#pragma unroll
        for (int dt = 0; dt < 8; dt++) {
            O[dt][0] *= sc0; O[dt][1] *= sc0;
            O[dt][2] *= sc1; O[dt][3] *= sc1;
        }

#pragma unroll
        for (int kk = 0; kk < 4; kk++) {
            uint32_t pah[4];
            {
                __half2 p0 = __floats2half2_rn(s[2 * kk][0], s[2 * kk][1]);
                __half2 p1 = __floats2half2_rn(s[2 * kk][2], s[2 * kk][3]);
                __half2 p2 = __floats2half2_rn(s[2 * kk + 1][0], s[2 * kk + 1][1]);
                __half2 p3 = __floats2half2_rn(s[2 * kk + 1][2], s[2 * kk + 1][3]);
                pah[0] = *reinterpret_cast<uint32_t*>(&p0);
                pah[1] = *reinterpret_cast<uint32_t*>(&p1);
                pah[2] = *reinterpret_cast<uint32_t*>(&p2);
                pah[3] = *reinterpret_cast<uint32_t*>(&p3);
            }
#pragma unroll
            for (int dg = 0; dg < 4; dg++) {
                uint32_t bh[4], bl[4];
                const int drow = dg * 16 + br_l;
                const uint32_t bo = swz128(drow, 2 * kk + b_ch);
                ldsm4(bh, sb + AT_VTH + bo);
                ldsm4(bl, sb + AT_VTL + bo);
                mma16816(O[2 * dg],     pah, bh);
                mma16816(O[2 * dg + 1], pah, bh + 2);
                mma16816(O[2 * dg],     pah, bl);
                mma16816(O[2 * dg + 1], pah, bl + 2);
            }
        }
    }

    const float inv0 = 1.0f / lsum0, inv1 = 1.0f / lsum1;
    const size_t row0 = brow + qt * 64 + w * 16 + gid;
    const size_t row1 = row0 + 8;
#pragma unroll
    for (int dt = 0; dt < 8; dt++) {
        const int col = h * 64 + dt * 8 + 2 * tig;
        __half2 h0 = __floats2half2_rn(O[dt][0] * inv0, O[dt][1] * inv0);
        __half2 h1 = __floats2half2_rn(O[dt][2] * inv1, O[dt][3] * inv1);
        *(__half2*)(Oh + row0 * D_MODEL + col) = h0;
        *(__half2*)(Oh + row1 * D_MODEL + col) = h1;
    }
}

// ---------------- fused residual add + LayerNorm + optional fp16 out --------
__global__ __launch_bounds__(256)
void add_ln_kernel(const float* __restrict__ x,
                   const float* __restrict__ r,
                   const float* __restrict__ g,
                   const float* __restrict__ bta,
                   float* __restrict__ y,
                   __half* __restrict__ H,
                   int write_h) {
    const int row = blockIdx.x;
    const int tid = threadIdx.x;
    const int c = tid * 4;
    const size_t idx = (size_t)row * D_MODEL + c;

    float4 xv = *(const float4*)(x + idx);
    float4 rv = *(const float4*)(r + idx);
    float4 v;
    v.x = xv.x + rv.x; v.y = xv.y + rv.y;
    v.z = xv.z + rv.z; v.w = xv.w + rv.w;

    float s = v.x + v.y + v.z + v.w;
    float ss = fmaf(v.x, v.x, fmaf(v.y, v.y, fmaf(v.z, v.z, v.w * v.w)));

    __shared__ float rs[256], rss[256];
    rs[tid] = s; rss[tid] = ss;
    __syncthreads();
    for (int off = 128; off > 0; off >>= 1) {
        if (tid < off) { rs[tid] += rs[tid + off]; rss[tid] += rss[tid + off]; }
        __syncthreads();
    }
    float mean = rs[0] * (1.0f / D_MODEL);
    float var = rss[0] * (1.0f / D_MODEL) - mean * mean;
    float inv = rsqrtf(var + 1e-5f);

    float4 gg = *(const float4*)(g + c);
    float4 bb = *(const float4*)(bta + c);
    float4 o;
    o.x = (v.x - mean) * inv * gg.x + bb.x;
    o.y = (v.y - mean) * inv * gg.y + bb.y;
    o.z = (v.z - mean) * inv * gg.z + bb.z;
    o.w = (v.w - mean) * inv * gg.w + bb.w;
    *(float4*)(y + idx) = o;
    if (write_h) store_h4(H, idx, o);
}

// ---------------- host orchestration ---------------------------------------
extern "C" void kernel_launch(void* const* d_in, const int* in_sizes, int n_in,
                              void* d_out, int out_size) {
    const int*   src  = (const int*)d_in[0];
    const int*   mask = (const int*)d_in[1];
    const float* emb  = (const float*)d_in[2];
    const float* pe   = (const float*)d_in[3];
    const float* wq = (const float*)d_in[4];
    const float* bq = (const float*)d_in[5];
    const float* wk = (const float*)d_in[6];
    const float* bk = (const float*)d_in[7];
    const float* wv = (const float*)d_in[8];
    const float* bv = (const float*)d_in[9];
    const float* wo = (const float*)d_in[10];
    const float* bo = (const float*)d_in[11];
    const float* w1 = (const float*)d_in[12];
    const float* b1 = (const float*)d_in[13];
    const float* w2 = (const float*)d_in[14];
    const float* b2 = (const float*)d_in[15];
    const float* g1  = (const float*)d_in[16];
    const float* be1 = (const float*)d_in[17];
    const float* g2  = (const float*)d_in[18];
    const float* be2 = (const float*)d_in[19];
    float* out = (float*)d_out;

    float *px, *pt, *pbqkv;
    cudaGetSymbolAddress((void**)&px, g_x);
    cudaGetSymbolAddress((void**)&pt, g_t);
    cudaGetSymbolAddress((void**)&pbqkv, g_bqkv);

    __half *qkvh, *qkvl, *ah, *hh;
    cudaGetSymbolAddress((void**)&qkvh, g_qkvh);
    cudaGetSymbolAddress((void**)&qkvl, g_qkvl);
    cudaGetSymbolAddress((void**)&ah, g_ah);
    cudaGetSymbolAddress((void**)&hh, g_hh);

    __half *wqkvt, *wot, *w1t, *w2t;
    cudaGetSymbolAddress((void**)&wqkvt, g_wqkvt);
    cudaGetSymbolAddress((void**)&wot, g_wot);
    cudaGetSymbolAddress((void**)&w1t, g_w1t);
    cudaGetSymbolAddress((void**)&w2t, g_w2t);

    static int attr_set = 0;
    if (!attr_set) {
        cudaFuncSetAttribute(gemm_tc<1, 0>,
                             cudaFuncAttributeMaxDynamicSharedMemorySize,
                             GEMM_SMEM_BYTES);
        cudaFuncSetAttribute(gemm_tc<2, 1>,
                             cudaFuncAttributeMaxDynamicSharedMemorySize,
                             GEMM_SMEM_BYTES);
        cudaFuncSetAttribute(gemm_tc<0, 0>,
                             cudaFuncAttributeMaxDynamicSharedMemorySize,
                             GEMM_SMEM_BYTES);
        cudaFuncSetAttribute(attn_mma_kernel,
                             cudaFuncAttributeMaxDynamicSharedMemorySize,
                             ATT_SMEM_BYTES);
        attr_set = 1;
    }

    // ---- weight prep: ONE launch ----
    prep_weights_kernel<<<dim3(12288, 1, 6), dim3(32, 8)>>>(
        wq, wk, wv, wo, w1, w2, wqkvt, wot, w1t, w2t);
    concat_bias_kernel<<<dim3(12, 6), 256>>>(bq, bk, bv, pbqkv);

    embed_kernel<<<ROWS, 256>>>(src, emb, pe, px, ah);

    dim3 g_qkv_grid(3072 / 128, ROWS / 128);   // (24, 32)
    dim3 g_dd(D_MODEL / 128, ROWS / 128);      // (8, 32)
    dim3 g_ff(D_FF / 128,    ROWS / 128);      // (32, 32)
    dim3 attn_grid(SEQ / 64, N_HEADS, BATCH);

    for (int l = 0; l < N_LAYERS; l++) {
        size_t woqkv = (size_t)l * 3072 * 1024;
        size_t wofs  = (size_t)l * 1024 * 1024;
        size_t bofs  = (size_t)l * D_MODEL;
        size_t wfofs = (size_t)l * 4096 * 1024;
        size_t b1ofs = (size_t)l * D_FF;

        // QKV projection (single-term A) -> fp16 hi/lo outputs
        gemm_tc<1, 0><<<g_qkv_grid, 256, GEMM_SMEM_BYTES>>>(
            ah, wqkvt + woqkv, pbqkv + l * 3072,
            nullptr, qkvh, qkvl, ROWS, 3072, 1024);

        // flash attention (S: Qh.Kh, AV: Ph.(Vh+Vl)) -> fp16 hi
        attn_mma_kernel<<<attn_grid, 128, ATT_SMEM_BYTES>>>(
            qkvh, qkvl, mask, ah);

        // O projection (single-term A) -> fp32
        gemm_tc<0, 0><<<g_dd, 256, GEMM_SMEM_BYTES>>>(
            ah, wot + wofs, bo + bofs,
            pt, nullptr, nullptr, ROWS, 1024, 1024);

        add_ln_kernel<<<ROWS, 256>>>(px, pt, g1 + bofs, be1 + bofs, px, ah, 1);

        // FFN1: single-term A, relu, fp16 out
        gemm_tc<2, 1><<<g_ff, 256, GEMM_SMEM_BYTES>>>(
            ah, w1t + wfofs, b1 + b1ofs,
            nullptr, hh, nullptr, ROWS, 4096, 1024);

        // FFN2: single-term A -> fp32
        gemm_tc<0, 0><<<g_dd, 256, GEMM_SMEM_BYTES>>>(
            hh, w2t + wfofs, b2 + bofs,
            pt, nullptr, nullptr, ROWS, 1024, 4096);

        if (l == N_LAYERS - 1) {
            add_ln_kernel<<<ROWS, 256>>>(px, pt, g2 + bofs, be2 + bofs, out,
                                         ah, 0);
        } else {
            add_ln_kernel<<<ROWS, 256>>>(px, pt, g2 + bofs, be2 + bofs, px,
                                         ah, 1);
        }
    }
}